// round 12
// baseline (speedup 1.0000x reference)
#include <cuda_runtime.h>
#include <cuda_fp16.h>
#include <math.h>
#include <cstdint>

#define Bq 2
#define Tq 4096
#define DIMq 2048
#define Hq 16
#define HKVq 4
#define HDq 128
#define NREPq 4
#define Rq 16
#define NBq 256
#define TOPKq 64
#define Mq (Bq * Tq)
#define NQKV 3072

// ---------------- scratch ----------------
__device__ __half g_k[Mq * HKVq * HDq];
__device__ __half g_v[Mq * HKVq * HDq];
__device__ float g_xmean_part[Bq * 16 * DIMq];
__device__ float g_xmean[Bq * DIMq];
__device__ float g_kimean[Bq * HDq];
__device__ float g_u[Bq * DIMq];
__device__ float g_scores[Bq * NBq];
__device__ int   g_topk[Bq * TOPKq];
__device__ float2 g_trig[Tq * 64];

__device__ __half g_qh[Mq * DIMq];
__device__ __half g_kselh[Bq * HKVq * TOPKq * HDq];
__device__ __half g_vselhT[Bq * HKVq * HDq * TOPKq];
__device__ __half g_xh[Mq * DIMq];
__device__ __half g_xoh[Mq * DIMq];
__device__ __half g_wqkvT[NQKV * DIMq];
__device__ __half g_woT[DIMq * DIMq];

// ---------------- helpers ----------------
__device__ __forceinline__ uint32_t smem_u32(const void* p) {
    uint32_t a;
    asm("{ .reg .u64 t; cvta.to.shared.u64 t, %1; cvt.u32.u64 %0, t; }" : "=r"(a) : "l"(p));
    return a;
}
__device__ __forceinline__ void cp16(uint32_t dst, const void* src) {
    asm volatile("cp.async.cg.shared.global [%0], [%1], 16;" :: "r"(dst), "l"(src));
}
__device__ __forceinline__ void ldsm4(uint32_t& r0, uint32_t& r1, uint32_t& r2, uint32_t& r3,
                                      uint32_t addr) {
    asm volatile("ldmatrix.sync.aligned.m8n8.x4.shared.b16 {%0,%1,%2,%3}, [%4];"
                 : "=r"(r0), "=r"(r1), "=r"(r2), "=r"(r3) : "r"(addr));
}
__device__ __forceinline__ void mma16816(float& c0, float& c1, float& c2, float& c3,
                                         uint32_t a0, uint32_t a1, uint32_t a2, uint32_t a3,
                                         uint32_t b0, uint32_t b1) {
    asm volatile(
        "mma.sync.aligned.m16n8k16.row.col.f32.f16.f16.f32 "
        "{%0,%1,%2,%3}, {%4,%5,%6,%7}, {%8,%9}, {%0,%1,%2,%3};"
        : "+f"(c0), "+f"(c1), "+f"(c2), "+f"(c3)
        : "r"(a0), "r"(a1), "r"(a2), "r"(a3), "r"(b0), "r"(b1));
}

// ---------------- GEMM core ----------------
#define NSTAGE 3
#define STAGE_BYTES 32768
#define GEMM_SMEM (NSTAGE * STAGE_BYTES)

#define GEMM_MAINLOOP(A_, Bt_, K_)                                                  \
    const int nchunks = (K_) >> 6;                                                  \
    const int wm = (wid & 3) << 5;                                                  \
    const int wn = (wid >> 2) << 6;                                                 \
    float acc[2][8][4];                                                             \
    _Pragma("unroll") for (int i = 0; i < 2; i++)                                   \
        _Pragma("unroll") for (int j = 0; j < 8; j++)                               \
            _Pragma("unroll") for (int c = 0; c < 4; c++) acc[i][j][c] = 0.f;       \
    auto produce = [&](int ci) {                                                    \
        const int slot = ci % NSTAGE;                                               \
        const int kk = ci << 6;                                                     \
        const uint32_t sA = tiles + slot * STAGE_BYTES;                             \
        const uint32_t sB = sA + 16384;                                             \
        _Pragma("unroll") for (int i = 0; i < 4; i++) {                             \
            int ch = tid + (i << 8);                                                \
            int row = ch >> 3;                                                      \
            int c = ch & 7;                                                         \
            uint32_t soff = (row << 7) + (((c ^ (row & 7))) << 4);                  \
            cp16(sA + soff, (A_) + (size_t)(brow + row) * (K_) + kk + c * 8);       \
            cp16(sB + soff, (Bt_) + (size_t)(bcol + row) * (K_) + kk + c * 8);      \
        }                                                                           \
        asm volatile("cp.async.commit_group;" ::: "memory");                        \
    };                                                                              \
    produce(0);                                                                     \
    produce(1);                                                                     \
    for (int ci = 0; ci < nchunks; ci++) {                                          \
        if (ci + 1 < nchunks)                                                       \
            asm volatile("cp.async.wait_group 1;" ::: "memory");                    \
        else                                                                        \
            asm volatile("cp.async.wait_group 0;" ::: "memory");                    \
        __syncthreads();                                                            \
        if (ci + 2 < nchunks) produce(ci + 2);                                      \
        const int slot = ci % NSTAGE;                                               \
        const uint32_t sA = tiles + slot * STAGE_BYTES;                             \
        const uint32_t sB = sA + 16384;                                             \
        _Pragma("unroll") for (int ks = 0; ks < 4; ks++) {                          \
            const int kc = (ks << 1) + (lane >> 4);                                 \
            uint32_t a[2][4];                                                       \
            _Pragma("unroll") for (int ma = 0; ma < 2; ma++) {                      \
                int row = wm + (ma << 4) + (lane & 15);                             \
                uint32_t addr = sA + (row << 7) + ((kc ^ (row & 7)) << 4);          \
                ldsm4(a[ma][0], a[ma][1], a[ma][2], a[ma][3], addr);                \
            }                                                                       \
            uint32_t b[4][4];                                                       \
            _Pragma("unroll") for (int nb = 0; nb < 4; nb++) {                      \
                int row = wn + (nb << 4) + (lane & 15);                             \
                uint32_t addr = sB + (row << 7) + ((kc ^ (row & 7)) << 4);          \
                ldsm4(b[nb][0], b[nb][1], b[nb][2], b[nb][3], addr);                \
            }                                                                       \
            _Pragma("unroll") for (int ma = 0; ma < 2; ma++)                        \
                _Pragma("unroll") for (int j = 0; j < 8; j++) {                     \
                    int nb = j >> 1, sel = j & 1;                                   \
                    mma16816(acc[ma][j][0], acc[ma][j][1], acc[ma][j][2],           \
                             acc[ma][j][3], a[ma][0], a[ma][1], a[ma][2],           \
                             a[ma][3], b[nb][sel], b[nb][sel + 2]);                 \
                }                                                                   \
        }                                                                           \
    }

// fused QKV projection + RoPE epilogue; bcol0/brow0 select tile windows
__global__ __launch_bounds__(256, 2)
void gemm_qkv(const __half* __restrict__ A, const __half* __restrict__ Bt,
              int bcol0, int brow0) {
    extern __shared__ char smem[];
    const uint32_t tiles = smem_u32(smem);
    const int tid = threadIdx.x;
    const int wid = tid >> 5;
    const int lane = tid & 31;
    const int brow = (blockIdx.y << 7) + brow0;
    const int bcol = (blockIdx.x + bcol0) << 7;

    GEMM_MAINLOOP(A, Bt, DIMq)

    const int g = lane >> 2;
    const int tg = lane & 3;
    __half* Cout;
    int cbase, cstride;
    bool dorope;
    if (bcol < 2048)      { Cout = g_qh; cbase = bcol;        cstride = 2048; dorope = true; }
    else if (bcol < 2560) { Cout = g_k;  cbase = bcol - 2048; cstride = 512;  dorope = true; }
    else                  { Cout = g_v;  cbase = bcol - 2560; cstride = 512;  dorope = false; }
#pragma unroll
    for (int ma = 0; ma < 2; ma++) {
#pragma unroll
        for (int j = 0; j < 8; j++) {
            int row = brow + wm + (ma << 4) + g;
            int col = cbase + wn + (j << 3) + (tg << 1);
            float2 lo = make_float2(acc[ma][j][0], acc[ma][j][1]);
            float2 hi = make_float2(acc[ma][j][2], acc[ma][j][3]);
            if (dorope) {
                int p = (col & 127) >> 1;
                float2 c1 = g_trig[((row & (Tq - 1)) << 6) + p];
                float2 c2 = g_trig[(((row + 8) & (Tq - 1)) << 6) + p];
                lo = make_float2(lo.x * c1.x - lo.y * c1.y, lo.x * c1.y + lo.y * c1.x);
                hi = make_float2(hi.x * c2.x - hi.y * c2.y, hi.x * c2.y + hi.y * c2.x);
            }
            *reinterpret_cast<__half2*>(Cout + (size_t)row * cstride + col) =
                __floats2half2_rn(lo.x, lo.y);
            *reinterpret_cast<__half2*>(Cout + (size_t)(row + 8) * cstride + col) =
                __floats2half2_rn(hi.x, hi.y);
        }
    }
}

// generic GEMM (output projection), row-window via brow0
__global__ __launch_bounds__(256, 2)
void gemm_f16(const __half* __restrict__ A, const __half* __restrict__ Bt,
              float* __restrict__ C, int N, int K, int brow0) {
    extern __shared__ char smem[];
    const uint32_t tiles = smem_u32(smem);
    const int tid = threadIdx.x;
    const int wid = tid >> 5;
    const int lane = tid & 31;
    const int brow = (blockIdx.y << 7) + brow0;
    const int bcol = blockIdx.x << 7;

    GEMM_MAINLOOP(A, Bt, K)

    const int g = lane >> 2;
    const int tg = lane & 3;
#pragma unroll
    for (int ma = 0; ma < 2; ma++) {
#pragma unroll
        for (int j = 0; j < 8; j++) {
            int row = brow + wm + (ma << 4) + g;
            int col = bcol + wn + (j << 3) + (tg << 1);
            float2 lo = make_float2(acc[ma][j][0], acc[ma][j][1]);
            float2 hi = make_float2(acc[ma][j][2], acc[ma][j][3]);
            *reinterpret_cast<float2*>(C + (size_t)row * N + col) = lo;
            *reinterpret_cast<float2*>(C + (size_t)(row + 8) * N + col) = hi;
        }
    }
}

// ---------------- fp32 -> fp16 convert ----------------
__global__ void conv_h(const float* __restrict__ src, __half* __restrict__ dst, size_t n) {
    size_t i = ((size_t)blockIdx.x * blockDim.x + threadIdx.x) * 4;
    size_t stride = (size_t)gridDim.x * blockDim.x * 4;
    for (; i < n; i += stride) {
        float4 v = *reinterpret_cast<const float4*>(src + i);
        *reinterpret_cast<__half2*>(dst + i) = __floats2half2_rn(v.x, v.y);
        *reinterpret_cast<__half2*>(dst + i + 2) = __floats2half2_rn(v.z, v.w);
    }
}

// transpose + convert: w [K,N] fp32 -> wT [N,K] fp16
__global__ void transpose_h(const float* __restrict__ w, __half* __restrict__ wT,
                            int K, int N) {
    __shared__ float t[32][33];
    int n0 = blockIdx.x << 5, k0 = blockIdx.y << 5;
    int tx = threadIdx.x, ty = threadIdx.y;
#pragma unroll
    for (int j = 0; j < 4; j++)
        t[ty + j * 8][tx] = w[(size_t)(k0 + ty + j * 8) * N + n0 + tx];
    __syncthreads();
#pragma unroll
    for (int j = 0; j < 4; j++) {
        int n = n0 + ty + j * 8;
        wT[(size_t)n * K + k0 + tx] = __float2half(t[tx][ty + j * 8]);
    }
}

// ---------------- trig table ----------------
__global__ void trig_table_kernel() {
    int idx = blockIdx.x * blockDim.x + threadIdx.x;
    if (idx >= Tq * 64) return;
    int p = idx & 63;
    int t = idx >> 6;
    double freq = exp(-((double)p / 64.0) * log(10000.0));
    double ang = (double)t * freq;
    double sd, cd;
    sincos(ang, &sd, &cd);
    g_trig[idx] = make_float2((float)cd, (float)sd);
}

// ---------------- compress only selected blocks ----------------
__global__ void compress_sel(const float* __restrict__ cwa, const float* __restrict__ cwb) {
    int j = blockIdx.x % TOPKq;
    int hk = (blockIdx.x / TOPKq) % HKVq;
    int b = blockIdx.x / (TOPKq * HKVq);
    int bhk = b * HKVq + hk;
    int n = g_topk[b * TOPKq + j];
    __shared__ float kb[Rq][HDq + 4];
    __shared__ float vb[Rq][HDq + 4];
    __shared__ float sa[Rq], sb[Rq], w[Rq];
    int d = threadIdx.x;
    for (int r = 0; r < Rq; r++) {
        int t = n * Rq + r;
        size_t off = ((size_t)(b * Tq + t)) * (HKVq * HDq) + hk * HDq + d;
        kb[r][d] = __half2float(g_k[off]);
        vb[r][d] = __half2float(g_v[off]);
    }
    __syncthreads();
    {
        int grp = d >> 3, sub = d & 7;
        float da = 0.f, db = 0.f;
        for (int i = sub; i < HDq; i += 8) {
            float kv = kb[grp][i];
            da = fmaf(kv, __ldg(cwa + i), da);
            db = fmaf(kv, __ldg(cwb + i), db);
        }
#pragma unroll
        for (int o = 4; o > 0; o >>= 1) {
            da += __shfl_down_sync(0xffffffffu, da, o, 8);
            db += __shfl_down_sync(0xffffffffu, db, o, 8);
        }
        if (sub == 0) { sa[grp] = da; sb[grp] = db; }
    }
    __syncthreads();
    if (d < 16) {
        float a = sa[d], bb = sb[d];
        float ma = a, mb = bb;
#pragma unroll
        for (int o = 8; o > 0; o >>= 1) {
            ma = fmaxf(ma, __shfl_xor_sync(0x0000ffffu, ma, o, 16));
            mb = fmaxf(mb, __shfl_xor_sync(0x0000ffffu, mb, o, 16));
        }
        float ea = expf(a - ma), eb = expf(bb - mb);
        float sua = ea, sub2 = eb;
#pragma unroll
        for (int o = 8; o > 0; o >>= 1) {
            sua += __shfl_xor_sync(0x0000ffffu, sua, o, 16);
            sub2 += __shfl_xor_sync(0x0000ffffu, sub2, o, 16);
        }
        w[d] = 0.5f * (ea / sua + eb / sub2);
    }
    __syncthreads();
    float ck = 0.f, cv = 0.f;
#pragma unroll
    for (int r = 0; r < Rq; r++) {
        ck = fmaf(w[r], kb[r][d], ck);
        cv = fmaf(w[r], vb[r][d], cv);
    }
    g_kselh[((size_t)bhk * TOPKq + j) * HDq + d] = __float2half(ck);
    g_vselhT[(size_t)bhk * HDq * TOPKq + (size_t)d * TOPKq + j] = __float2half(cv);
}

// ---------------- selection chain ----------------
__global__ void xmean_part_kernel(const float* __restrict__ x) {
    int b = blockIdx.z;
    int chunk = blockIdx.y;
    int c = blockIdx.x * 128 + threadIdx.x;
    float s = 0.f;
    for (int tt = chunk * 256; tt < (chunk + 1) * 256; tt++)
        s += x[((size_t)(b * Tq + tt)) * DIMq + c];
    g_xmean_part[((size_t)(b * 16 + chunk)) * DIMq + c] = s;
}
__global__ void xmean_final_kernel() {
    int b = blockIdx.x / 16;
    int c = (blockIdx.x % 16) * 128 + threadIdx.x;
    float s = 0.f;
    for (int ch = 0; ch < 16; ch++) s += g_xmean_part[((size_t)(b * 16 + ch)) * DIMq + c];
    g_xmean[b * DIMq + c] = s * (1.0f / (float)Tq);
}
__global__ void kimean_kernel(const float* __restrict__ wik) {
    int b = blockIdx.x;
    int d = threadIdx.x;
    float s = 0.f;
    for (int c = 0; c < DIMq; c++) s += g_xmean[b * DIMq + c] * wik[(size_t)c * HDq + d];
    g_kimean[b * HDq + d] = s;
}
__global__ void u_kernel(const float* __restrict__ wiq) {
    int b = blockIdx.x / 16;
    int c = (blockIdx.x % 16) * 128 + threadIdx.x;
    float s = 0.f;
    for (int d = 0; d < HDq; d++) s += wiq[(size_t)c * HDq + d] * g_kimean[b * HDq + d];
    g_u[b * DIMq + c] = s;
}
__global__ void scores_kernel(const float* __restrict__ x) {
    int t = blockIdx.x % NBq;
    int b = blockIdx.x / NBq;
    __shared__ float red[128];
    float s = 0.f;
    const float* xp = x + ((size_t)(b * Tq + t)) * DIMq;
    const float* up = g_u + b * DIMq;
    for (int c = threadIdx.x; c < DIMq; c += 128) s += xp[c] * up[c];
    red[threadIdx.x] = s;
    __syncthreads();
    for (int off = 64; off > 0; off >>= 1) {
        if (threadIdx.x < off) red[threadIdx.x] += red[threadIdx.x + off];
        __syncthreads();
    }
    if (threadIdx.x == 0) g_scores[b * NBq + t] = red[0];
}
__global__ void topk_kernel() {
    int b = blockIdx.x;
    int t = threadIdx.x;
    __shared__ float sc[256];
    sc[t] = g_scores[b * NBq + t];
    __syncthreads();
    float v = sc[t];
    int rank = 0;
    for (int j = 0; j < 256; j++) {
        float o = sc[j];
        rank += (o > v) || (o == v && j < t);
    }
    if (rank < TOPKq) g_topk[b * TOPKq + rank] = t;
}

// ---------------- tensor-core attention (per-batch launch via b0) ----------------
#define AQ_OFF 0
#define AK_OFF 16384
#define AV_OFF 32768
#define AP_OFF 49152
#define ARM_OFF 57344
#define ARS_OFF 57856
#define ATTN_SMEM2 58368

__global__ __launch_bounds__(256)
void attn_mma(int b0) {
    extern __shared__ char sm[];
    const uint32_t base = smem_u32(sm);
    const int tid = threadIdx.x;
    const int wid = tid >> 5;
    const int lane = tid & 31;
    const int ntile = Tq / 64;
    int tile = blockIdx.x % ntile;
    int hk = blockIdx.x / ntile;
    int b = b0;
    const int bhk = b * HKVq + hk;

    const __half* kp = g_kselh + (size_t)bhk * TOPKq * HDq;
    const __half* vtp = g_vselhT + (size_t)bhk * HDq * TOPKq;

    for (int i = tid; i < 1024; i += 256) {
        int r = i >> 4, c = i & 15;
        *reinterpret_cast<uint4*>(sm + AK_OFF + ((c >> 3) << 13) + (r << 7) +
                                  (((c & 7) ^ (r & 7)) << 4)) =
            *reinterpret_cast<const uint4*>(kp + r * HDq + c * 8);
    }
    for (int i = tid; i < 1024; i += 256) {
        int r = i >> 3, c = i & 7;
        *reinterpret_cast<uint4*>(sm + AV_OFF + (r << 7) + ((c ^ (r & 7)) << 4)) =
            *reinterpret_cast<const uint4*>(vtp + r * TOPKq + c * 8);
    }
    __syncthreads();

    float* redm = reinterpret_cast<float*>(sm + ARM_OFF);
    float* reds = reinterpret_cast<float*>(sm + ARS_OFF);

    const int wm = (wid & 3) << 4;
    const int wn2 = wid >> 2;
    const int g = lane >> 2, tg = lane & 3;
    const int arow = wm + (lane & 15);
    const float scale = 0.08838834764831845f;
    const int qrow0 = b * Tq + tile * 64;

    for (int hi = 0; hi < NREPq; hi++) {
        int h = hk * NREPq + hi;
        for (int i = tid; i < 1024; i += 256) {
            int r = i >> 4, c = i & 15;
            *reinterpret_cast<uint4*>(sm + AQ_OFF + ((c >> 3) << 13) + (r << 7) +
                                      (((c & 7) ^ (r & 7)) << 4)) =
                *reinterpret_cast<const uint4*>(g_qh + (size_t)(qrow0 + r) * DIMq + h * HDq + c * 8);
        }
        __syncthreads();

        float sacc[4][4];
#pragma unroll
        for (int nb = 0; nb < 4; nb++)
#pragma unroll
            for (int c = 0; c < 4; c++) sacc[nb][c] = 0.f;
#pragma unroll
        for (int ks = 0; ks < 8; ks++) {
            int t2 = ks >> 2;
            int kc = ((ks & 3) << 1) + (lane >> 4);
            uint32_t a0, a1, a2, a3;
            ldsm4(a0, a1, a2, a3,
                  base + AQ_OFF + (t2 << 13) + (arow << 7) + ((kc ^ (arow & 7)) << 4));
            uint32_t bf[2][4];
#pragma unroll
            for (int nb2 = 0; nb2 < 2; nb2++) {
                int brw = wn2 * 32 + nb2 * 16 + (lane & 15);
                ldsm4(bf[nb2][0], bf[nb2][1], bf[nb2][2], bf[nb2][3],
                      base + AK_OFF + (t2 << 13) + (brw << 7) + ((kc ^ (brw & 7)) << 4));
            }
#pragma unroll
            for (int nb = 0; nb < 4; nb++) {
                int nb2 = nb >> 1, sel = nb & 1;
                mma16816(sacc[nb][0], sacc[nb][1], sacc[nb][2], sacc[nb][3],
                         a0, a1, a2, a3, bf[nb2][sel], bf[nb2][sel + 2]);
            }
        }
        float m0 = -1e30f, m1 = -1e30f;
#pragma unroll
        for (int nb = 0; nb < 4; nb++) {
#pragma unroll
            for (int c = 0; c < 4; c++) sacc[nb][c] *= scale;
            m0 = fmaxf(m0, fmaxf(sacc[nb][0], sacc[nb][1]));
            m1 = fmaxf(m1, fmaxf(sacc[nb][2], sacc[nb][3]));
        }
        m0 = fmaxf(m0, __shfl_xor_sync(0xffffffffu, m0, 1));
        m0 = fmaxf(m0, __shfl_xor_sync(0xffffffffu, m0, 2));
        m1 = fmaxf(m1, __shfl_xor_sync(0xffffffffu, m1, 1));
        m1 = fmaxf(m1, __shfl_xor_sync(0xffffffffu, m1, 2));
        if (tg == 0) {
            redm[wn2 * 64 + wm + g] = m0;
            redm[wn2 * 64 + wm + g + 8] = m1;
        }
        __syncthreads();
        float M0 = fmaxf(redm[wm + g], redm[64 + wm + g]);
        float M1 = fmaxf(redm[wm + g + 8], redm[64 + wm + g + 8]);
        float s0 = 0.f, s1 = 0.f;
#pragma unroll
        for (int nb = 0; nb < 4; nb++) {
            sacc[nb][0] = expf(sacc[nb][0] - M0);
            sacc[nb][1] = expf(sacc[nb][1] - M0);
            sacc[nb][2] = expf(sacc[nb][2] - M1);
            sacc[nb][3] = expf(sacc[nb][3] - M1);
            s0 += sacc[nb][0] + sacc[nb][1];
            s1 += sacc[nb][2] + sacc[nb][3];
        }
        s0 += __shfl_xor_sync(0xffffffffu, s0, 1);
        s0 += __shfl_xor_sync(0xffffffffu, s0, 2);
        s1 += __shfl_xor_sync(0xffffffffu, s1, 1);
        s1 += __shfl_xor_sync(0xffffffffu, s1, 2);
        if (tg == 0) {
            reds[wn2 * 64 + wm + g] = s0;
            reds[wn2 * 64 + wm + g + 8] = s1;
        }
        __syncthreads();
        float inv0 = 1.f / (reds[wm + g] + reds[64 + wm + g]);
        float inv1 = 1.f / (reds[wm + g + 8] + reds[64 + wm + g + 8]);
#pragma unroll
        for (int nb = 0; nb < 4; nb++) {
            int chunk = wn2 * 4 + nb;
            int r0 = wm + g, r1 = wm + g + 8;
            *reinterpret_cast<__half2*>(sm + AP_OFF + (r0 << 7) +
                                        ((chunk ^ (r0 & 7)) << 4) + (tg << 2)) =
                __floats2half2_rn(sacc[nb][0] * inv0, sacc[nb][1] * inv0);
            *reinterpret_cast<__half2*>(sm + AP_OFF + (r1 << 7) +
                                        ((chunk ^ (r1 & 7)) << 4) + (tg << 2)) =
                __floats2half2_rn(sacc[nb][2] * inv1, sacc[nb][3] * inv1);
        }
        __syncthreads();
        float oacc[8][4];
#pragma unroll
        for (int j = 0; j < 8; j++)
#pragma unroll
            for (int c = 0; c < 4; c++) oacc[j][c] = 0.f;
#pragma unroll
        for (int ks = 0; ks < 4; ks++) {
            int kc = (ks << 1) + (lane >> 4);
            uint32_t a0, a1, a2, a3;
            ldsm4(a0, a1, a2, a3,
                  base + AP_OFF + (arow << 7) + ((kc ^ (arow & 7)) << 4));
            uint32_t bf[4][4];
#pragma unroll
            for (int nb2 = 0; nb2 < 4; nb2++) {
                int brw = wn2 * 64 + nb2 * 16 + (lane & 15);
                ldsm4(bf[nb2][0], bf[nb2][1], bf[nb2][2], bf[nb2][3],
                      base + AV_OFF + (brw << 7) + ((kc ^ (brw & 7)) << 4));
            }
#pragma unroll
            for (int j = 0; j < 8; j++) {
                int nb2 = j >> 1, sel = j & 1;
                mma16816(oacc[j][0], oacc[j][1], oacc[j][2], oacc[j][3],
                         a0, a1, a2, a3, bf[nb2][sel], bf[nb2][sel + 2]);
            }
        }
#pragma unroll
        for (int j = 0; j < 8; j++) {
            int col = wn2 * 64 + (j << 3) + (tg << 1);
            int r0 = tile * 64 + wm + g;
            __half* o0 = g_xoh + (size_t)(b * Tq + r0) * DIMq + h * HDq + col;
            *reinterpret_cast<__half2*>(o0) = __floats2half2_rn(oacc[j][0], oacc[j][1]);
            *reinterpret_cast<__half2*>(o0 + (size_t)8 * DIMq) =
                __floats2half2_rn(oacc[j][2], oacc[j][3]);
        }
        __syncthreads();
    }
}

// ---------------- launch (pipelined batch-split tail) ----------------
extern "C" void kernel_launch(void* const* d_in, const int* in_sizes, int n_in,
                              void* d_out, int out_size) {
    const float* x   = (const float*)d_in[0];
    const float* wq  = (const float*)d_in[1];
    const float* wk  = (const float*)d_in[2];
    const float* wv  = (const float*)d_in[3];
    const float* wo  = (const float*)d_in[4];
    const float* wiq = (const float*)d_in[5];
    const float* wik = (const float*)d_in[6];
    const float* cwa = (const float*)d_in[7];
    const float* cwb = (const float*)d_in[8];
    float* out = (float*)d_out;

    static cudaStream_t s2 = nullptr, s3 = nullptr;
    static cudaEvent_t eFork = nullptr, eT = nullptr, eKV = nullptr, eWo = nullptr;
    static cudaEvent_t eQ0 = nullptr, eQ1 = nullptr, eA0 = nullptr, eA1 = nullptr;
    if (!s2) {
        cudaStreamCreateWithFlags(&s2, cudaStreamNonBlocking);
        cudaStreamCreateWithFlags(&s3, cudaStreamNonBlocking);
        cudaEventCreateWithFlags(&eFork, cudaEventDisableTiming);
        cudaEventCreateWithFlags(&eT, cudaEventDisableTiming);
        cudaEventCreateWithFlags(&eKV, cudaEventDisableTiming);
        cudaEventCreateWithFlags(&eWo, cudaEventDisableTiming);
        cudaEventCreateWithFlags(&eQ0, cudaEventDisableTiming);
        cudaEventCreateWithFlags(&eQ1, cudaEventDisableTiming);
        cudaEventCreateWithFlags(&eA0, cudaEventDisableTiming);
        cudaEventCreateWithFlags(&eA1, cudaEventDisableTiming);
        cudaFuncSetAttribute(gemm_qkv, cudaFuncAttributeMaxDynamicSharedMemorySize, GEMM_SMEM);
        cudaFuncSetAttribute(gemm_f16, cudaFuncAttributeMaxDynamicSharedMemorySize, GEMM_SMEM);
        cudaFuncSetAttribute(attn_mma, cudaFuncAttributeMaxDynamicSharedMemorySize, ATTN_SMEM2);
    }

    __half *xh, *xoh, *wqkvT, *woT;
    cudaGetSymbolAddress((void**)&xh, g_xh);
    cudaGetSymbolAddress((void**)&xoh, g_xoh);
    cudaGetSymbolAddress((void**)&wqkvT, g_wqkvT);
    cudaGetSymbolAddress((void**)&woT, g_woT);

    // fork
    cudaEventRecord(eFork, 0);
    cudaStreamWaitEvent(s2, eFork, 0);
    cudaStreamWaitEvent(s3, eFork, 0);

    // s2: trig + QKV weight transposes, then wo transpose
    trig_table_kernel<<<(Tq * 64 + 255) / 256, 256, 0, s2>>>();
    transpose_h<<<dim3(DIMq / 32, DIMq / 32), dim3(32, 8), 0, s2>>>(wq, wqkvT, DIMq, DIMq);
    transpose_h<<<dim3((HKVq * HDq) / 32, DIMq / 32), dim3(32, 8), 0, s2>>>(
        wk, wqkvT + (size_t)2048 * DIMq, DIMq, HKVq * HDq);
    transpose_h<<<dim3((HKVq * HDq) / 32, DIMq / 32), dim3(32, 8), 0, s2>>>(
        wv, wqkvT + (size_t)2560 * DIMq, DIMq, HKVq * HDq);
    cudaEventRecord(eT, s2);
    transpose_h<<<dim3(DIMq / 32, DIMq / 32), dim3(32, 8), 0, s2>>>(wo, woT, DIMq, DIMq);
    cudaEventRecord(eWo, s2);

    // s3: selection prefix (needs only x)
    xmean_part_kernel<<<dim3(16, 16, Bq), 128, 0, s3>>>(x);
    xmean_final_kernel<<<Bq * 16, 128, 0, s3>>>();
    kimean_kernel<<<Bq, 128, 0, s3>>>(wik);
    u_kernel<<<Bq * 16, 128, 0, s3>>>(wiq);
    scores_kernel<<<Bq * NBq, 128, 0, s3>>>(x);
    topk_kernel<<<Bq, 256, 0, s3>>>();

    // main: conv + KV GEMM
    conv_h<<<2048, 256>>>(x, xh, (size_t)Mq * DIMq);
    cudaStreamWaitEvent(0, eT, 0);
    gemm_qkv<<<dim3(8, Mq / 128), 256, GEMM_SMEM>>>(xh, wqkvT, 16, 0);   // K, V (all rows)
    cudaEventRecord(eKV, 0);

    // s3: selected-only compress (after eKV record)
    cudaStreamWaitEvent(s3, eKV, 0);
    compress_sel<<<Bq * HKVq * TOPKq, 128, 0, s3>>>(cwa, cwb);

    // main: Q GEMM batch 0 (rows 0..4095)
    gemm_qkv<<<dim3(16, Tq / 128), 256, GEMM_SMEM>>>(xh, wqkvT, 0, 0);
    cudaEventRecord(eQ0, 0);

    // s3: attn b=0 (after compress in-order; waits eQ0) — overlaps Q GEMM batch 1
    cudaStreamWaitEvent(s3, eQ0, 0);
    attn_mma<<<HKVq * (Tq / 64), 256, ATTN_SMEM2, s3>>>(0);
    cudaEventRecord(eA0, s3);

    // main: Q GEMM batch 1 (rows 4096..8191)
    gemm_qkv<<<dim3(16, Tq / 128), 256, GEMM_SMEM>>>(xh, wqkvT, 0, Tq);
    cudaEventRecord(eQ1, 0);

    // s3: attn b=1 (waits eQ1) — overlaps wo GEMM batch 0
    cudaStreamWaitEvent(s3, eQ1, 0);
    attn_mma<<<HKVq * (Tq / 64), 256, ATTN_SMEM2, s3>>>(1);
    cudaEventRecord(eA1, s3);

    // main: wo GEMM batch 0 (rows 0..4095) after attn b=0 + woT
    cudaStreamWaitEvent(0, eA0, 0);
    cudaStreamWaitEvent(0, eWo, 0);
    gemm_f16<<<dim3(DIMq / 128, Tq / 128), 256, GEMM_SMEM>>>(xoh, woT, out, DIMq, DIMq, 0);

    // main: wo GEMM batch 1 after attn b=1 (joins s3)
    cudaStreamWaitEvent(0, eA1, 0);
    gemm_f16<<<dim3(DIMq / 128, Tq / 128), 256, GEMM_SMEM>>>(xoh, woT, out, DIMq, DIMq, Tq);
}

// round 13
// speedup vs baseline: 1.0715x; 1.0715x over previous
#include <cuda_runtime.h>
#include <cuda_fp16.h>
#include <math.h>
#include <cstdint>

#define Bq 2
#define Tq 4096
#define DIMq 2048
#define Hq 16
#define HKVq 4
#define HDq 128
#define NREPq 4
#define Rq 16
#define NBq 256
#define TOPKq 64
#define Mq (Bq * Tq)
#define NQKV 3072

// ---------------- scratch ----------------
__device__ __half g_k[Mq * HKVq * HDq];
__device__ __half g_v[Mq * HKVq * HDq];
__device__ float g_xmean_part[Bq * 16 * DIMq];
__device__ float g_xmean[Bq * DIMq];
__device__ float g_kimean[Bq * HDq];
__device__ float g_u[Bq * DIMq];
__device__ float g_scores[Bq * NBq];
__device__ int   g_topk[Bq * TOPKq];
__device__ float2 g_trig[Tq * 64];

__device__ __half g_qh[Mq * DIMq];
__device__ __half g_kselh[Bq * HKVq * TOPKq * HDq];
__device__ __half g_vselhT[Bq * HKVq * HDq * TOPKq];
__device__ __half g_xh[Mq * DIMq];
__device__ __half g_xoh[Mq * DIMq];
__device__ __half g_wqkvT[NQKV * DIMq];
__device__ __half g_woT[DIMq * DIMq];

// ---------------- helpers ----------------
__device__ __forceinline__ uint32_t smem_u32(const void* p) {
    uint32_t a;
    asm("{ .reg .u64 t; cvta.to.shared.u64 t, %1; cvt.u32.u64 %0, t; }" : "=r"(a) : "l"(p));
    return a;
}
__device__ __forceinline__ void cp16(uint32_t dst, const void* src) {
    asm volatile("cp.async.cg.shared.global [%0], [%1], 16;" :: "r"(dst), "l"(src));
}
__device__ __forceinline__ void ldsm4(uint32_t& r0, uint32_t& r1, uint32_t& r2, uint32_t& r3,
                                      uint32_t addr) {
    asm volatile("ldmatrix.sync.aligned.m8n8.x4.shared.b16 {%0,%1,%2,%3}, [%4];"
                 : "=r"(r0), "=r"(r1), "=r"(r2), "=r"(r3) : "r"(addr));
}
__device__ __forceinline__ void mma16816(float& c0, float& c1, float& c2, float& c3,
                                         uint32_t a0, uint32_t a1, uint32_t a2, uint32_t a3,
                                         uint32_t b0, uint32_t b1) {
    asm volatile(
        "mma.sync.aligned.m16n8k16.row.col.f32.f16.f16.f32 "
        "{%0,%1,%2,%3}, {%4,%5,%6,%7}, {%8,%9}, {%0,%1,%2,%3};"
        : "+f"(c0), "+f"(c1), "+f"(c2), "+f"(c3)
        : "r"(a0), "r"(a1), "r"(a2), "r"(a3), "r"(b0), "r"(b1));
}

// ---------------- GEMM core ----------------
#define NSTAGE 3
#define STAGE_BYTES 32768
#define GEMM_SMEM (NSTAGE * STAGE_BYTES)

#define GEMM_MAINLOOP(A_, Bt_, K_)                                                  \
    const int nchunks = (K_) >> 6;                                                  \
    const int wm = (wid & 3) << 5;                                                  \
    const int wn = (wid >> 2) << 6;                                                 \
    float acc[2][8][4];                                                             \
    _Pragma("unroll") for (int i = 0; i < 2; i++)                                   \
        _Pragma("unroll") for (int j = 0; j < 8; j++)                               \
            _Pragma("unroll") for (int c = 0; c < 4; c++) acc[i][j][c] = 0.f;       \
    auto produce = [&](int ci) {                                                    \
        const int slot = ci % NSTAGE;                                               \
        const int kk = ci << 6;                                                     \
        const uint32_t sA = tiles + slot * STAGE_BYTES;                             \
        const uint32_t sB = sA + 16384;                                             \
        _Pragma("unroll") for (int i = 0; i < 4; i++) {                             \
            int ch = tid + (i << 8);                                                \
            int row = ch >> 3;                                                      \
            int c = ch & 7;                                                         \
            uint32_t soff = (row << 7) + (((c ^ (row & 7))) << 4);                  \
            cp16(sA + soff, (A_) + (size_t)(brow + row) * (K_) + kk + c * 8);       \
            cp16(sB + soff, (Bt_) + (size_t)(bcol + row) * (K_) + kk + c * 8);      \
        }                                                                           \
        asm volatile("cp.async.commit_group;" ::: "memory");                        \
    };                                                                              \
    produce(0);                                                                     \
    produce(1);                                                                     \
    for (int ci = 0; ci < nchunks; ci++) {                                          \
        if (ci + 1 < nchunks)                                                       \
            asm volatile("cp.async.wait_group 1;" ::: "memory");                    \
        else                                                                        \
            asm volatile("cp.async.wait_group 0;" ::: "memory");                    \
        __syncthreads();                                                            \
        if (ci + 2 < nchunks) produce(ci + 2);                                      \
        const int slot = ci % NSTAGE;                                               \
        const uint32_t sA = tiles + slot * STAGE_BYTES;                             \
        const uint32_t sB = sA + 16384;                                             \
        _Pragma("unroll") for (int ks = 0; ks < 4; ks++) {                          \
            const int kc = (ks << 1) + (lane >> 4);                                 \
            uint32_t a[2][4];                                                       \
            _Pragma("unroll") for (int ma = 0; ma < 2; ma++) {                      \
                int row = wm + (ma << 4) + (lane & 15);                             \
                uint32_t addr = sA + (row << 7) + ((kc ^ (row & 7)) << 4);          \
                ldsm4(a[ma][0], a[ma][1], a[ma][2], a[ma][3], addr);                \
            }                                                                       \
            uint32_t b[4][4];                                                       \
            _Pragma("unroll") for (int nb = 0; nb < 4; nb++) {                      \
                int row = wn + (nb << 4) + (lane & 15);                             \
                uint32_t addr = sB + (row << 7) + ((kc ^ (row & 7)) << 4);          \
                ldsm4(b[nb][0], b[nb][1], b[nb][2], b[nb][3], addr);                \
            }                                                                       \
            _Pragma("unroll") for (int ma = 0; ma < 2; ma++)                        \
                _Pragma("unroll") for (int j = 0; j < 8; j++) {                     \
                    int nb = j >> 1, sel = j & 1;                                   \
                    mma16816(acc[ma][j][0], acc[ma][j][1], acc[ma][j][2],           \
                             acc[ma][j][3], a[ma][0], a[ma][1], a[ma][2],           \
                             a[ma][3], b[nb][sel], b[nb][sel + 2]);                 \
                }                                                                   \
        }                                                                           \
    }

// fused QKV projection + RoPE epilogue; bcol0 = col window, brow0 = row window
__global__ __launch_bounds__(256, 2)
void gemm_qkv(const __half* __restrict__ A, const __half* __restrict__ Bt,
              int bcol0, int brow0) {
    extern __shared__ char smem[];
    const uint32_t tiles = smem_u32(smem);
    const int tid = threadIdx.x;
    const int wid = tid >> 5;
    const int lane = tid & 31;
    const int brow = (blockIdx.y << 7) + brow0;
    const int bcol = (blockIdx.x + bcol0) << 7;

    GEMM_MAINLOOP(A, Bt, DIMq)

    const int g = lane >> 2;
    const int tg = lane & 3;
    __half* Cout;
    int cbase, cstride;
    bool dorope;
    if (bcol < 2048)      { Cout = g_qh; cbase = bcol;        cstride = 2048; dorope = true; }
    else if (bcol < 2560) { Cout = g_k;  cbase = bcol - 2048; cstride = 512;  dorope = true; }
    else                  { Cout = g_v;  cbase = bcol - 2560; cstride = 512;  dorope = false; }
#pragma unroll
    for (int ma = 0; ma < 2; ma++) {
#pragma unroll
        for (int j = 0; j < 8; j++) {
            int row = brow + wm + (ma << 4) + g;
            int col = cbase + wn + (j << 3) + (tg << 1);
            float2 lo = make_float2(acc[ma][j][0], acc[ma][j][1]);
            float2 hi = make_float2(acc[ma][j][2], acc[ma][j][3]);
            if (dorope) {
                int p = (col & 127) >> 1;
                float2 c1 = g_trig[((row & (Tq - 1)) << 6) + p];
                float2 c2 = g_trig[(((row + 8) & (Tq - 1)) << 6) + p];
                lo = make_float2(lo.x * c1.x - lo.y * c1.y, lo.x * c1.y + lo.y * c1.x);
                hi = make_float2(hi.x * c2.x - hi.y * c2.y, hi.x * c2.y + hi.y * c2.x);
            }
            *reinterpret_cast<__half2*>(Cout + (size_t)row * cstride + col) =
                __floats2half2_rn(lo.x, lo.y);
            *reinterpret_cast<__half2*>(Cout + (size_t)(row + 8) * cstride + col) =
                __floats2half2_rn(hi.x, hi.y);
        }
    }
}

// generic GEMM (output projection)
__global__ __launch_bounds__(256, 2)
void gemm_f16(const __half* __restrict__ A, const __half* __restrict__ Bt,
              float* __restrict__ C, int N, int K) {
    extern __shared__ char smem[];
    const uint32_t tiles = smem_u32(smem);
    const int tid = threadIdx.x;
    const int wid = tid >> 5;
    const int lane = tid & 31;
    const int brow = blockIdx.y << 7;
    const int bcol = blockIdx.x << 7;

    GEMM_MAINLOOP(A, Bt, K)

    const int g = lane >> 2;
    const int tg = lane & 3;
#pragma unroll
    for (int ma = 0; ma < 2; ma++) {
#pragma unroll
        for (int j = 0; j < 8; j++) {
            int row = brow + wm + (ma << 4) + g;
            int col = bcol + wn + (j << 3) + (tg << 1);
            float2 lo = make_float2(acc[ma][j][0], acc[ma][j][1]);
            float2 hi = make_float2(acc[ma][j][2], acc[ma][j][3]);
            *reinterpret_cast<float2*>(C + (size_t)row * N + col) = lo;
            *reinterpret_cast<float2*>(C + (size_t)(row + 8) * N + col) = hi;
        }
    }
}

// ---------------- fp32 -> fp16 convert ----------------
__global__ void conv_h(const float* __restrict__ src, __half* __restrict__ dst, size_t n) {
    size_t i = ((size_t)blockIdx.x * blockDim.x + threadIdx.x) * 4;
    size_t stride = (size_t)gridDim.x * blockDim.x * 4;
    for (; i < n; i += stride) {
        float4 v = *reinterpret_cast<const float4*>(src + i);
        *reinterpret_cast<__half2*>(dst + i) = __floats2half2_rn(v.x, v.y);
        *reinterpret_cast<__half2*>(dst + i + 2) = __floats2half2_rn(v.z, v.w);
    }
}

// transpose + convert: w [K,N] fp32 -> wT [N,K] fp16
__global__ void transpose_h(const float* __restrict__ w, __half* __restrict__ wT,
                            int K, int N) {
    __shared__ float t[32][33];
    int n0 = blockIdx.x << 5, k0 = blockIdx.y << 5;
    int tx = threadIdx.x, ty = threadIdx.y;
#pragma unroll
    for (int j = 0; j < 4; j++)
        t[ty + j * 8][tx] = w[(size_t)(k0 + ty + j * 8) * N + n0 + tx];
    __syncthreads();
#pragma unroll
    for (int j = 0; j < 4; j++) {
        int n = n0 + ty + j * 8;
        wT[(size_t)n * K + k0 + tx] = __float2half(t[tx][ty + j * 8]);
    }
}

// ---------------- trig table ----------------
__global__ void trig_table_kernel() {
    int idx = blockIdx.x * blockDim.x + threadIdx.x;
    if (idx >= Tq * 64) return;
    int p = idx & 63;
    int t = idx >> 6;
    double freq = exp(-((double)p / 64.0) * log(10000.0));
    double ang = (double)t * freq;
    double sd, cd;
    sincos(ang, &sd, &cd);
    g_trig[idx] = make_float2((float)cd, (float)sd);
}

// ---------------- compress only selected blocks ----------------
__global__ void compress_sel(const float* __restrict__ cwa, const float* __restrict__ cwb) {
    int j = blockIdx.x % TOPKq;
    int hk = (blockIdx.x / TOPKq) % HKVq;
    int b = blockIdx.x / (TOPKq * HKVq);
    int bhk = b * HKVq + hk;
    int n = g_topk[b * TOPKq + j];
    __shared__ float kb[Rq][HDq + 4];
    __shared__ float vb[Rq][HDq + 4];
    __shared__ float sa[Rq], sb[Rq], w[Rq];
    int d = threadIdx.x;
    for (int r = 0; r < Rq; r++) {
        int t = n * Rq + r;
        size_t off = ((size_t)(b * Tq + t)) * (HKVq * HDq) + hk * HDq + d;
        kb[r][d] = __half2float(g_k[off]);
        vb[r][d] = __half2float(g_v[off]);
    }
    __syncthreads();
    {
        int grp = d >> 3, sub = d & 7;
        float da = 0.f, db = 0.f;
        for (int i = sub; i < HDq; i += 8) {
            float kv = kb[grp][i];
            da = fmaf(kv, __ldg(cwa + i), da);
            db = fmaf(kv, __ldg(cwb + i), db);
        }
#pragma unroll
        for (int o = 4; o > 0; o >>= 1) {
            da += __shfl_down_sync(0xffffffffu, da, o, 8);
            db += __shfl_down_sync(0xffffffffu, db, o, 8);
        }
        if (sub == 0) { sa[grp] = da; sb[grp] = db; }
    }
    __syncthreads();
    if (d < 16) {
        float a = sa[d], bb = sb[d];
        float ma = a, mb = bb;
#pragma unroll
        for (int o = 8; o > 0; o >>= 1) {
            ma = fmaxf(ma, __shfl_xor_sync(0x0000ffffu, ma, o, 16));
            mb = fmaxf(mb, __shfl_xor_sync(0x0000ffffu, mb, o, 16));
        }
        float ea = expf(a - ma), eb = expf(bb - mb);
        float sua = ea, sub2 = eb;
#pragma unroll
        for (int o = 8; o > 0; o >>= 1) {
            sua += __shfl_xor_sync(0x0000ffffu, sua, o, 16);
            sub2 += __shfl_xor_sync(0x0000ffffu, sub2, o, 16);
        }
        w[d] = 0.5f * (ea / sua + eb / sub2);
    }
    __syncthreads();
    float ck = 0.f, cv = 0.f;
#pragma unroll
    for (int r = 0; r < Rq; r++) {
        ck = fmaf(w[r], kb[r][d], ck);
        cv = fmaf(w[r], vb[r][d], cv);
    }
    g_kselh[((size_t)bhk * TOPKq + j) * HDq + d] = __float2half(ck);
    g_vselhT[(size_t)bhk * HDq * TOPKq + (size_t)d * TOPKq + j] = __float2half(cv);
}

// ---------------- selection chain ----------------
__global__ void xmean_part_kernel(const float* __restrict__ x) {
    int b = blockIdx.z;
    int chunk = blockIdx.y;
    int c = blockIdx.x * 128 + threadIdx.x;
    float s = 0.f;
    for (int tt = chunk * 256; tt < (chunk + 1) * 256; tt++)
        s += x[((size_t)(b * Tq + tt)) * DIMq + c];
    g_xmean_part[((size_t)(b * 16 + chunk)) * DIMq + c] = s;
}
__global__ void xmean_final_kernel() {
    int b = blockIdx.x / 16;
    int c = (blockIdx.x % 16) * 128 + threadIdx.x;
    float s = 0.f;
    for (int ch = 0; ch < 16; ch++) s += g_xmean_part[((size_t)(b * 16 + ch)) * DIMq + c];
    g_xmean[b * DIMq + c] = s * (1.0f / (float)Tq);
}
__global__ void kimean_kernel(const float* __restrict__ wik) {
    int b = blockIdx.x;
    int d = threadIdx.x;
    float s = 0.f;
    for (int c = 0; c < DIMq; c++) s += g_xmean[b * DIMq + c] * wik[(size_t)c * HDq + d];
    g_kimean[b * HDq + d] = s;
}
__global__ void u_kernel(const float* __restrict__ wiq) {
    int b = blockIdx.x / 16;
    int c = (blockIdx.x % 16) * 128 + threadIdx.x;
    float s = 0.f;
    for (int d = 0; d < HDq; d++) s += wiq[(size_t)c * HDq + d] * g_kimean[b * HDq + d];
    g_u[b * DIMq + c] = s;
}
__global__ void scores_kernel(const float* __restrict__ x) {
    int t = blockIdx.x % NBq;
    int b = blockIdx.x / NBq;
    __shared__ float red[128];
    float s = 0.f;
    const float* xp = x + ((size_t)(b * Tq + t)) * DIMq;
    const float* up = g_u + b * DIMq;
    for (int c = threadIdx.x; c < DIMq; c += 128) s += xp[c] * up[c];
    red[threadIdx.x] = s;
    __syncthreads();
    for (int off = 64; off > 0; off >>= 1) {
        if (threadIdx.x < off) red[threadIdx.x] += red[threadIdx.x + off];
        __syncthreads();
    }
    if (threadIdx.x == 0) g_scores[b * NBq + t] = red[0];
}
__global__ void topk_kernel() {
    int b = blockIdx.x;
    int t = threadIdx.x;
    __shared__ float sc[256];
    sc[t] = g_scores[b * NBq + t];
    __syncthreads();
    float v = sc[t];
    int rank = 0;
    for (int j = 0; j < 256; j++) {
        float o = sc[j];
        rank += (o > v) || (o == v && j < t);
    }
    if (rank < TOPKq) g_topk[b * TOPKq + rank] = t;
}

// ---------------- tensor-core attention ----------------
#define AQ_OFF 0
#define AK_OFF 16384
#define AV_OFF 32768
#define AP_OFF 49152
#define ARM_OFF 57344
#define ARS_OFF 57856
#define ATTN_SMEM2 58368

__global__ __launch_bounds__(256)
void attn_mma() {
    extern __shared__ char sm[];
    const uint32_t base = smem_u32(sm);
    const int tid = threadIdx.x;
    const int wid = tid >> 5;
    const int lane = tid & 31;
    const int ntile = Tq / 64;
    int tile = blockIdx.x % ntile;
    int hk = (blockIdx.x / ntile) % HKVq;
    int b = blockIdx.x / (ntile * HKVq);
    const int bhk = b * HKVq + hk;

    const __half* kp = g_kselh + (size_t)bhk * TOPKq * HDq;
    const __half* vtp = g_vselhT + (size_t)bhk * HDq * TOPKq;

    for (int i = tid; i < 1024; i += 256) {
        int r = i >> 4, c = i & 15;
        *reinterpret_cast<uint4*>(sm + AK_OFF + ((c >> 3) << 13) + (r << 7) +
                                  (((c & 7) ^ (r & 7)) << 4)) =
            *reinterpret_cast<const uint4*>(kp + r * HDq + c * 8);
    }
    for (int i = tid; i < 1024; i += 256) {
        int r = i >> 3, c = i & 7;
        *reinterpret_cast<uint4*>(sm + AV_OFF + (r << 7) + ((c ^ (r & 7)) << 4)) =
            *reinterpret_cast<const uint4*>(vtp + r * TOPKq + c * 8);
    }
    __syncthreads();

    float* redm = reinterpret_cast<float*>(sm + ARM_OFF);
    float* reds = reinterpret_cast<float*>(sm + ARS_OFF);

    const int wm = (wid & 3) << 4;
    const int wn2 = wid >> 2;
    const int g = lane >> 2, tg = lane & 3;
    const int arow = wm + (lane & 15);
    const float scale = 0.08838834764831845f;
    const int qrow0 = b * Tq + tile * 64;

    for (int hi = 0; hi < NREPq; hi++) {
        int h = hk * NREPq + hi;
        for (int i = tid; i < 1024; i += 256) {
            int r = i >> 4, c = i & 15;
            *reinterpret_cast<uint4*>(sm + AQ_OFF + ((c >> 3) << 13) + (r << 7) +
                                      (((c & 7) ^ (r & 7)) << 4)) =
                *reinterpret_cast<const uint4*>(g_qh + (size_t)(qrow0 + r) * DIMq + h * HDq + c * 8);
        }
        __syncthreads();

        float sacc[4][4];
#pragma unroll
        for (int nb = 0; nb < 4; nb++)
#pragma unroll
            for (int c = 0; c < 4; c++) sacc[nb][c] = 0.f;
#pragma unroll
        for (int ks = 0; ks < 8; ks++) {
            int t2 = ks >> 2;
            int kc = ((ks & 3) << 1) + (lane >> 4);
            uint32_t a0, a1, a2, a3;
            ldsm4(a0, a1, a2, a3,
                  base + AQ_OFF + (t2 << 13) + (arow << 7) + ((kc ^ (arow & 7)) << 4));
            uint32_t bf[2][4];
#pragma unroll
            for (int nb2 = 0; nb2 < 2; nb2++) {
                int brw = wn2 * 32 + nb2 * 16 + (lane & 15);
                ldsm4(bf[nb2][0], bf[nb2][1], bf[nb2][2], bf[nb2][3],
                      base + AK_OFF + (t2 << 13) + (brw << 7) + ((kc ^ (brw & 7)) << 4));
            }
#pragma unroll
            for (int nb = 0; nb < 4; nb++) {
                int nb2 = nb >> 1, sel = nb & 1;
                mma16816(sacc[nb][0], sacc[nb][1], sacc[nb][2], sacc[nb][3],
                         a0, a1, a2, a3, bf[nb2][sel], bf[nb2][sel + 2]);
            }
        }
        float m0 = -1e30f, m1 = -1e30f;
#pragma unroll
        for (int nb = 0; nb < 4; nb++) {
#pragma unroll
            for (int c = 0; c < 4; c++) sacc[nb][c] *= scale;
            m0 = fmaxf(m0, fmaxf(sacc[nb][0], sacc[nb][1]));
            m1 = fmaxf(m1, fmaxf(sacc[nb][2], sacc[nb][3]));
        }
        m0 = fmaxf(m0, __shfl_xor_sync(0xffffffffu, m0, 1));
        m0 = fmaxf(m0, __shfl_xor_sync(0xffffffffu, m0, 2));
        m1 = fmaxf(m1, __shfl_xor_sync(0xffffffffu, m1, 1));
        m1 = fmaxf(m1, __shfl_xor_sync(0xffffffffu, m1, 2));
        if (tg == 0) {
            redm[wn2 * 64 + wm + g] = m0;
            redm[wn2 * 64 + wm + g + 8] = m1;
        }
        __syncthreads();
        float M0 = fmaxf(redm[wm + g], redm[64 + wm + g]);
        float M1 = fmaxf(redm[wm + g + 8], redm[64 + wm + g + 8]);
        float s0 = 0.f, s1 = 0.f;
#pragma unroll
        for (int nb = 0; nb < 4; nb++) {
            sacc[nb][0] = expf(sacc[nb][0] - M0);
            sacc[nb][1] = expf(sacc[nb][1] - M0);
            sacc[nb][2] = expf(sacc[nb][2] - M1);
            sacc[nb][3] = expf(sacc[nb][3] - M1);
            s0 += sacc[nb][0] + sacc[nb][1];
            s1 += sacc[nb][2] + sacc[nb][3];
        }
        s0 += __shfl_xor_sync(0xffffffffu, s0, 1);
        s0 += __shfl_xor_sync(0xffffffffu, s0, 2);
        s1 += __shfl_xor_sync(0xffffffffu, s1, 1);
        s1 += __shfl_xor_sync(0xffffffffu, s1, 2);
        if (tg == 0) {
            reds[wn2 * 64 + wm + g] = s0;
            reds[wn2 * 64 + wm + g + 8] = s1;
        }
        __syncthreads();
        float inv0 = 1.f / (reds[wm + g] + reds[64 + wm + g]);
        float inv1 = 1.f / (reds[wm + g + 8] + reds[64 + wm + g + 8]);
#pragma unroll
        for (int nb = 0; nb < 4; nb++) {
            int chunk = wn2 * 4 + nb;
            int r0 = wm + g, r1 = wm + g + 8;
            *reinterpret_cast<__half2*>(sm + AP_OFF + (r0 << 7) +
                                        ((chunk ^ (r0 & 7)) << 4) + (tg << 2)) =
                __floats2half2_rn(sacc[nb][0] * inv0, sacc[nb][1] * inv0);
            *reinterpret_cast<__half2*>(sm + AP_OFF + (r1 << 7) +
                                        ((chunk ^ (r1 & 7)) << 4) + (tg << 2)) =
                __floats2half2_rn(sacc[nb][2] * inv1, sacc[nb][3] * inv1);
        }
        __syncthreads();
        float oacc[8][4];
#pragma unroll
        for (int j = 0; j < 8; j++)
#pragma unroll
            for (int c = 0; c < 4; c++) oacc[j][c] = 0.f;
#pragma unroll
        for (int ks = 0; ks < 4; ks++) {
            int kc = (ks << 1) + (lane >> 4);
            uint32_t a0, a1, a2, a3;
            ldsm4(a0, a1, a2, a3,
                  base + AP_OFF + (arow << 7) + ((kc ^ (arow & 7)) << 4));
            uint32_t bf[4][4];
#pragma unroll
            for (int nb2 = 0; nb2 < 4; nb2++) {
                int brw = wn2 * 64 + nb2 * 16 + (lane & 15);
                ldsm4(bf[nb2][0], bf[nb2][1], bf[nb2][2], bf[nb2][3],
                      base + AV_OFF + (brw << 7) + ((kc ^ (brw & 7)) << 4));
            }
#pragma unroll
            for (int j = 0; j < 8; j++) {
                int nb2 = j >> 1, sel = j & 1;
                mma16816(oacc[j][0], oacc[j][1], oacc[j][2], oacc[j][3],
                         a0, a1, a2, a3, bf[nb2][sel], bf[nb2][sel + 2]);
            }
        }
#pragma unroll
        for (int j = 0; j < 8; j++) {
            int col = wn2 * 64 + (j << 3) + (tg << 1);
            int r0 = tile * 64 + wm + g;
            __half* o0 = g_xoh + (size_t)(b * Tq + r0) * DIMq + h * HDq + col;
            *reinterpret_cast<__half2*>(o0) = __floats2half2_rn(oacc[j][0], oacc[j][1]);
            *reinterpret_cast<__half2*>(o0 + (size_t)8 * DIMq) =
                __floats2half2_rn(oacc[j][2], oacc[j][3]);
        }
        __syncthreads();
    }
}

// ---------------- launch (R11 schedule + split conv, hidden second half) ----------------
extern "C" void kernel_launch(void* const* d_in, const int* in_sizes, int n_in,
                              void* d_out, int out_size) {
    const float* x   = (const float*)d_in[0];
    const float* wq  = (const float*)d_in[1];
    const float* wk  = (const float*)d_in[2];
    const float* wv  = (const float*)d_in[3];
    const float* wo  = (const float*)d_in[4];
    const float* wiq = (const float*)d_in[5];
    const float* wik = (const float*)d_in[6];
    const float* cwa = (const float*)d_in[7];
    const float* cwb = (const float*)d_in[8];
    float* out = (float*)d_out;

    static cudaStream_t s2 = nullptr, s3 = nullptr;
    static cudaEvent_t eFork = nullptr, eT = nullptr, eC1 = nullptr, eKV = nullptr,
                       eGa = nullptr, eWo = nullptr;
    if (!s2) {
        cudaStreamCreateWithFlags(&s2, cudaStreamNonBlocking);
        cudaStreamCreateWithFlags(&s3, cudaStreamNonBlocking);
        cudaEventCreateWithFlags(&eFork, cudaEventDisableTiming);
        cudaEventCreateWithFlags(&eT, cudaEventDisableTiming);
        cudaEventCreateWithFlags(&eC1, cudaEventDisableTiming);
        cudaEventCreateWithFlags(&eKV, cudaEventDisableTiming);
        cudaEventCreateWithFlags(&eGa, cudaEventDisableTiming);
        cudaEventCreateWithFlags(&eWo, cudaEventDisableTiming);
        cudaFuncSetAttribute(gemm_qkv, cudaFuncAttributeMaxDynamicSharedMemorySize, GEMM_SMEM);
        cudaFuncSetAttribute(gemm_f16, cudaFuncAttributeMaxDynamicSharedMemorySize, GEMM_SMEM);
        cudaFuncSetAttribute(attn_mma, cudaFuncAttributeMaxDynamicSharedMemorySize, ATTN_SMEM2);
    }

    __half *xh, *xoh, *wqkvT, *woT;
    cudaGetSymbolAddress((void**)&xh, g_xh);
    cudaGetSymbolAddress((void**)&xoh, g_xoh);
    cudaGetSymbolAddress((void**)&wqkvT, g_wqkvT);
    cudaGetSymbolAddress((void**)&woT, g_woT);

    const size_t halfElems = (size_t)Tq * DIMq;  // one batch worth

    // fork
    cudaEventRecord(eFork, 0);
    cudaStreamWaitEvent(s2, eFork, 0);
    cudaStreamWaitEvent(s3, eFork, 0);

    // s2: trig + QKV weight transposes, then conv second half, then wo transpose
    trig_table_kernel<<<(Tq * 64 + 255) / 256, 256, 0, s2>>>();
    transpose_h<<<dim3(DIMq / 32, DIMq / 32), dim3(32, 8), 0, s2>>>(wq, wqkvT, DIMq, DIMq);
    transpose_h<<<dim3((HKVq * HDq) / 32, DIMq / 32), dim3(32, 8), 0, s2>>>(
        wk, wqkvT + (size_t)2048 * DIMq, DIMq, HKVq * HDq);
    transpose_h<<<dim3((HKVq * HDq) / 32, DIMq / 32), dim3(32, 8), 0, s2>>>(
        wv, wqkvT + (size_t)2560 * DIMq, DIMq, HKVq * HDq);
    cudaEventRecord(eT, s2);
    conv_h<<<1024, 256, 0, s2>>>(x + halfElems, xh + halfElems, halfElems);   // batch 1
    cudaEventRecord(eC1, s2);
    transpose_h<<<dim3(DIMq / 32, DIMq / 32), dim3(32, 8), 0, s2>>>(wo, woT, DIMq, DIMq);
    cudaEventRecord(eWo, s2);

    // s3: selection prefix (needs only x)
    xmean_part_kernel<<<dim3(16, 16, Bq), 128, 0, s3>>>(x);
    xmean_final_kernel<<<Bq * 16, 128, 0, s3>>>();
    kimean_kernel<<<Bq, 128, 0, s3>>>(wik);
    u_kernel<<<Bq * 16, 128, 0, s3>>>(wiq);
    scores_kernel<<<Bq * NBq, 128, 0, s3>>>(x);
    topk_kernel<<<Bq, 256, 0, s3>>>();

    // main: conv batch 0; KV GEMM rows of batch 0 (overlaps conv batch 1 on s2)
    conv_h<<<1024, 256>>>(x, xh, halfElems);                                   // batch 0
    cudaStreamWaitEvent(0, eT, 0);
    gemm_qkv<<<dim3(8, Tq / 128), 256, GEMM_SMEM>>>(xh, wqkvT, 16, 0);        // KV rows b0
    cudaStreamWaitEvent(0, eC1, 0);
    gemm_qkv<<<dim3(8, Tq / 128), 256, GEMM_SMEM>>>(xh, wqkvT, 16, Tq);       // KV rows b1
    cudaEventRecord(eKV, 0);

    // s3: selected-only compress (enqueued after eKV record)
    cudaStreamWaitEvent(s3, eKV, 0);
    compress_sel<<<Bq * HKVq * TOPKq, 128, 0, s3>>>(cwa, cwb);
    cudaEventRecord(eGa, s3);

    // main: Q GEMM (all rows) overlaps compress; then attention; then output GEMM
    gemm_qkv<<<dim3(16, Mq / 128), 256, GEMM_SMEM>>>(xh, wqkvT, 0, 0);        // Q all
    cudaStreamWaitEvent(0, eGa, 0);
    attn_mma<<<Bq * HKVq * (Tq / 64), 256, ATTN_SMEM2>>>();
    cudaStreamWaitEvent(0, eWo, 0);
    gemm_f16<<<dim3(DIMq / 128, Mq / 128), 256, GEMM_SMEM>>>(xoh, woT, out, DIMq, DIMq);
}

// round 14
// speedup vs baseline: 1.1169x; 1.0424x over previous
#include <cuda_runtime.h>
#include <cuda_fp16.h>
#include <math.h>
#include <cstdint>

#define Bq 2
#define Tq 4096
#define DIMq 2048
#define Hq 16
#define HKVq 4
#define HDq 128
#define NREPq 4
#define Rq 16
#define NBq 256
#define TOPKq 64
#define Mq (Bq * Tq)
#define NQKV 3072

// ---------------- scratch ----------------
__device__ __half g_k[Mq * HKVq * HDq];
__device__ __half g_v[Mq * HKVq * HDq];
__device__ float g_xmean_part[Bq * 16 * DIMq];
__device__ float g_xmean[Bq * DIMq];
__device__ float g_kimean[Bq * HDq];
__device__ float g_u[Bq * DIMq];
__device__ float g_scores[Bq * NBq];
__device__ int   g_topk[Bq * TOPKq];
__device__ float2 g_trig[Tq * 64];

__device__ __half g_qh[Mq * DIMq];
__device__ __half g_kselh[Bq * HKVq * TOPKq * HDq];
__device__ __half g_vselhT[Bq * HKVq * HDq * TOPKq];
__device__ __half g_xh[Mq * DIMq];
__device__ __half g_xoh[Mq * DIMq];
__device__ __half g_wqkvT[NQKV * DIMq];
__device__ __half g_woT[DIMq * DIMq];

// ---------------- helpers ----------------
__device__ __forceinline__ uint32_t smem_u32(const void* p) {
    uint32_t a;
    asm("{ .reg .u64 t; cvta.to.shared.u64 t, %1; cvt.u32.u64 %0, t; }" : "=r"(a) : "l"(p));
    return a;
}
__device__ __forceinline__ void cp16(uint32_t dst, const void* src) {
    asm volatile("cp.async.cg.shared.global [%0], [%1], 16;" :: "r"(dst), "l"(src));
}
__device__ __forceinline__ void ldsm4(uint32_t& r0, uint32_t& r1, uint32_t& r2, uint32_t& r3,
                                      uint32_t addr) {
    asm volatile("ldmatrix.sync.aligned.m8n8.x4.shared.b16 {%0,%1,%2,%3}, [%4];"
                 : "=r"(r0), "=r"(r1), "=r"(r2), "=r"(r3) : "r"(addr));
}
__device__ __forceinline__ void mma16816(float& c0, float& c1, float& c2, float& c3,
                                         uint32_t a0, uint32_t a1, uint32_t a2, uint32_t a3,
                                         uint32_t b0, uint32_t b1) {
    asm volatile(
        "mma.sync.aligned.m16n8k16.row.col.f32.f16.f16.f32 "
        "{%0,%1,%2,%3}, {%4,%5,%6,%7}, {%8,%9}, {%0,%1,%2,%3};"
        : "+f"(c0), "+f"(c1), "+f"(c2), "+f"(c3)
        : "r"(a0), "r"(a1), "r"(a2), "r"(a3), "r"(b0), "r"(b1));
}

// ---------------- GEMM core ----------------
#define NSTAGE 3
#define STAGE_BYTES 32768
#define GEMM_SMEM (NSTAGE * STAGE_BYTES)

#define GEMM_MAINLOOP(A_, Bt_, K_)                                                  \
    const int nchunks = (K_) >> 6;                                                  \
    const int wm = (wid & 3) << 5;                                                  \
    const int wn = (wid >> 2) << 6;                                                 \
    float acc[2][8][4];                                                             \
    _Pragma("unroll") for (int i = 0; i < 2; i++)                                   \
        _Pragma("unroll") for (int j = 0; j < 8; j++)                               \
            _Pragma("unroll") for (int c = 0; c < 4; c++) acc[i][j][c] = 0.f;       \
    auto produce = [&](int ci) {                                                    \
        const int slot = ci % NSTAGE;                                               \
        const int kk = ci << 6;                                                     \
        const uint32_t sA = tiles + slot * STAGE_BYTES;                             \
        const uint32_t sB = sA + 16384;                                             \
        _Pragma("unroll") for (int i = 0; i < 4; i++) {                             \
            int ch = tid + (i << 8);                                                \
            int row = ch >> 3;                                                      \
            int c = ch & 7;                                                         \
            uint32_t soff = (row << 7) + (((c ^ (row & 7))) << 4);                  \
            cp16(sA + soff, (A_) + (size_t)(brow + row) * (K_) + kk + c * 8);       \
            cp16(sB + soff, (Bt_) + (size_t)(bcol + row) * (K_) + kk + c * 8);      \
        }                                                                           \
        asm volatile("cp.async.commit_group;" ::: "memory");                        \
    };                                                                              \
    produce(0);                                                                     \
    produce(1);                                                                     \
    for (int ci = 0; ci < nchunks; ci++) {                                          \
        if (ci + 1 < nchunks)                                                       \
            asm volatile("cp.async.wait_group 1;" ::: "memory");                    \
        else                                                                        \
            asm volatile("cp.async.wait_group 0;" ::: "memory");                    \
        __syncthreads();                                                            \
        if (ci + 2 < nchunks) produce(ci + 2);                                      \
        const int slot = ci % NSTAGE;                                               \
        const uint32_t sA = tiles + slot * STAGE_BYTES;                             \
        const uint32_t sB = sA + 16384;                                             \
        _Pragma("unroll") for (int ks = 0; ks < 4; ks++) {                          \
            const int kc = (ks << 1) + (lane >> 4);                                 \
            uint32_t a[2][4];                                                       \
            _Pragma("unroll") for (int ma = 0; ma < 2; ma++) {                      \
                int row = wm + (ma << 4) + (lane & 15);                             \
                uint32_t addr = sA + (row << 7) + ((kc ^ (row & 7)) << 4);          \
                ldsm4(a[ma][0], a[ma][1], a[ma][2], a[ma][3], addr);                \
            }                                                                       \
            uint32_t b[4][4];                                                       \
            _Pragma("unroll") for (int nb = 0; nb < 4; nb++) {                      \
                int row = wn + (nb << 4) + (lane & 15);                             \
                uint32_t addr = sB + (row << 7) + ((kc ^ (row & 7)) << 4);          \
                ldsm4(b[nb][0], b[nb][1], b[nb][2], b[nb][3], addr);                \
            }                                                                       \
            _Pragma("unroll") for (int ma = 0; ma < 2; ma++)                        \
                _Pragma("unroll") for (int j = 0; j < 8; j++) {                     \
                    int nb = j >> 1, sel = j & 1;                                   \
                    mma16816(acc[ma][j][0], acc[ma][j][1], acc[ma][j][2],           \
                             acc[ma][j][3], a[ma][0], a[ma][1], a[ma][2],           \
                             a[ma][3], b[nb][sel], b[nb][sel + 2]);                 \
                }                                                                   \
        }                                                                           \
    }

// fused QKV projection + RoPE epilogue; bcol0 selects Q (0) vs KV (16) launch
__global__ __launch_bounds__(256, 2)
void gemm_qkv(const __half* __restrict__ A, const __half* __restrict__ Bt, int bcol0) {
    extern __shared__ char smem[];
    const uint32_t tiles = smem_u32(smem);
    const int tid = threadIdx.x;
    const int wid = tid >> 5;
    const int lane = tid & 31;
    const int brow = blockIdx.y << 7;
    const int bcol = (blockIdx.x + bcol0) << 7;

    GEMM_MAINLOOP(A, Bt, DIMq)

    const int g = lane >> 2;
    const int tg = lane & 3;
    __half* Cout;
    int cbase, cstride;
    bool dorope;
    if (bcol < 2048)      { Cout = g_qh; cbase = bcol;        cstride = 2048; dorope = true; }
    else if (bcol < 2560) { Cout = g_k;  cbase = bcol - 2048; cstride = 512;  dorope = true; }
    else                  { Cout = g_v;  cbase = bcol - 2560; cstride = 512;  dorope = false; }
#pragma unroll
    for (int ma = 0; ma < 2; ma++) {
#pragma unroll
        for (int j = 0; j < 8; j++) {
            int row = brow + wm + (ma << 4) + g;
            int col = cbase + wn + (j << 3) + (tg << 1);
            float2 lo = make_float2(acc[ma][j][0], acc[ma][j][1]);
            float2 hi = make_float2(acc[ma][j][2], acc[ma][j][3]);
            if (dorope) {
                int p = (col & 127) >> 1;
                float2 c1 = g_trig[((row & (Tq - 1)) << 6) + p];
                float2 c2 = g_trig[(((row + 8) & (Tq - 1)) << 6) + p];
                lo = make_float2(lo.x * c1.x - lo.y * c1.y, lo.x * c1.y + lo.y * c1.x);
                hi = make_float2(hi.x * c2.x - hi.y * c2.y, hi.x * c2.y + hi.y * c2.x);
            }
            *reinterpret_cast<__half2*>(Cout + (size_t)row * cstride + col) =
                __floats2half2_rn(lo.x, lo.y);
            *reinterpret_cast<__half2*>(Cout + (size_t)(row + 8) * cstride + col) =
                __floats2half2_rn(hi.x, hi.y);
        }
    }
}

// generic GEMM (output projection)
__global__ __launch_bounds__(256, 2)
void gemm_f16(const __half* __restrict__ A, const __half* __restrict__ Bt,
              float* __restrict__ C, int N, int K) {
    extern __shared__ char smem[];
    const uint32_t tiles = smem_u32(smem);
    const int tid = threadIdx.x;
    const int wid = tid >> 5;
    const int lane = tid & 31;
    const int brow = blockIdx.y << 7;
    const int bcol = blockIdx.x << 7;

    GEMM_MAINLOOP(A, Bt, K)

    const int g = lane >> 2;
    const int tg = lane & 3;
#pragma unroll
    for (int ma = 0; ma < 2; ma++) {
#pragma unroll
        for (int j = 0; j < 8; j++) {
            int row = brow + wm + (ma << 4) + g;
            int col = bcol + wn + (j << 3) + (tg << 1);
            float2 lo = make_float2(acc[ma][j][0], acc[ma][j][1]);
            float2 hi = make_float2(acc[ma][j][2], acc[ma][j][3]);
            *reinterpret_cast<float2*>(C + (size_t)row * N + col) = lo;
            *reinterpret_cast<float2*>(C + (size_t)(row + 8) * N + col) = hi;
        }
    }
}

// ---------------- fp32 -> fp16 convert ----------------
__global__ void conv_h(const float* __restrict__ src, __half* __restrict__ dst, size_t n) {
    size_t i = ((size_t)blockIdx.x * blockDim.x + threadIdx.x) * 4;
    size_t stride = (size_t)gridDim.x * blockDim.x * 4;
    for (; i < n; i += stride) {
        float4 v = *reinterpret_cast<const float4*>(src + i);
        *reinterpret_cast<__half2*>(dst + i) = __floats2half2_rn(v.x, v.y);
        *reinterpret_cast<__half2*>(dst + i + 2) = __floats2half2_rn(v.z, v.w);
    }
}

// transpose + convert: w [K,N] fp32 -> wT [N,K] fp16
__global__ void transpose_h(const float* __restrict__ w, __half* __restrict__ wT,
                            int K, int N) {
    __shared__ float t[32][33];
    int n0 = blockIdx.x << 5, k0 = blockIdx.y << 5;
    int tx = threadIdx.x, ty = threadIdx.y;
#pragma unroll
    for (int j = 0; j < 4; j++)
        t[ty + j * 8][tx] = w[(size_t)(k0 + ty + j * 8) * N + n0 + tx];
    __syncthreads();
#pragma unroll
    for (int j = 0; j < 4; j++) {
        int n = n0 + ty + j * 8;
        wT[(size_t)n * K + k0 + tx] = __float2half(t[tx][ty + j * 8]);
    }
}

// ---------------- fast trig table: shared freqs + double range-reduce + sincosf ----------------
__global__ void trig_table_kernel() {
    __shared__ double freqs[64];
    int idx = blockIdx.x * blockDim.x + threadIdx.x;
    if (threadIdx.x < 64) {
        int p = threadIdx.x;
        freqs[p] = exp(-((double)p / 64.0) * log(10000.0));
    }
    __syncthreads();
    if (idx >= Tq * 64) return;
    int p = idx & 63;
    int t = idx >> 6;
    double ang = (double)t * freqs[p];
    const double twopi = 6.283185307179586476925286766559;
    double k = floor(ang * (1.0 / twopi));
    float r = (float)(ang - k * twopi);
    float sf, cf;
    sincosf(r, &sf, &cf);
    g_trig[idx] = make_float2(cf, sf);
}

// ---------------- compress only selected blocks ----------------
__global__ void compress_sel(const float* __restrict__ cwa, const float* __restrict__ cwb) {
    int j = blockIdx.x % TOPKq;
    int hk = (blockIdx.x / TOPKq) % HKVq;
    int b = blockIdx.x / (TOPKq * HKVq);
    int bhk = b * HKVq + hk;
    int n = g_topk[b * TOPKq + j];
    __shared__ float kb[Rq][HDq + 4];
    __shared__ float vb[Rq][HDq + 4];
    __shared__ float sa[Rq], sb[Rq], w[Rq];
    int d = threadIdx.x;
    for (int r = 0; r < Rq; r++) {
        int t = n * Rq + r;
        size_t off = ((size_t)(b * Tq + t)) * (HKVq * HDq) + hk * HDq + d;
        kb[r][d] = __half2float(g_k[off]);
        vb[r][d] = __half2float(g_v[off]);
    }
    __syncthreads();
    {
        int grp = d >> 3, sub = d & 7;
        float da = 0.f, db = 0.f;
        for (int i = sub; i < HDq; i += 8) {
            float kv = kb[grp][i];
            da = fmaf(kv, __ldg(cwa + i), da);
            db = fmaf(kv, __ldg(cwb + i), db);
        }
#pragma unroll
        for (int o = 4; o > 0; o >>= 1) {
            da += __shfl_down_sync(0xffffffffu, da, o, 8);
            db += __shfl_down_sync(0xffffffffu, db, o, 8);
        }
        if (sub == 0) { sa[grp] = da; sb[grp] = db; }
    }
    __syncthreads();
    if (d < 16) {
        float a = sa[d], bb = sb[d];
        float ma = a, mb = bb;
#pragma unroll
        for (int o = 8; o > 0; o >>= 1) {
            ma = fmaxf(ma, __shfl_xor_sync(0x0000ffffu, ma, o, 16));
            mb = fmaxf(mb, __shfl_xor_sync(0x0000ffffu, mb, o, 16));
        }
        float ea = expf(a - ma), eb = expf(bb - mb);
        float sua = ea, sub2 = eb;
#pragma unroll
        for (int o = 8; o > 0; o >>= 1) {
            sua += __shfl_xor_sync(0x0000ffffu, sua, o, 16);
            sub2 += __shfl_xor_sync(0x0000ffffu, sub2, o, 16);
        }
        w[d] = 0.5f * (ea / sua + eb / sub2);
    }
    __syncthreads();
    float ck = 0.f, cv = 0.f;
#pragma unroll
    for (int r = 0; r < Rq; r++) {
        ck = fmaf(w[r], kb[r][d], ck);
        cv = fmaf(w[r], vb[r][d], cv);
    }
    g_kselh[((size_t)bhk * TOPKq + j) * HDq + d] = __float2half(ck);
    g_vselhT[(size_t)bhk * HDq * TOPKq + (size_t)d * TOPKq + j] = __float2half(cv);
}

// ---------------- selection chain ----------------
__global__ void xmean_part_kernel(const float* __restrict__ x) {
    int b = blockIdx.z;
    int chunk = blockIdx.y;
    int c = blockIdx.x * 128 + threadIdx.x;
    float s = 0.f;
    for (int tt = chunk * 256; tt < (chunk + 1) * 256; tt++)
        s += x[((size_t)(b * Tq + tt)) * DIMq + c];
    g_xmean_part[((size_t)(b * 16 + chunk)) * DIMq + c] = s;
}
__global__ void xmean_final_kernel() {
    int b = blockIdx.x / 16;
    int c = (blockIdx.x % 16) * 128 + threadIdx.x;
    float s = 0.f;
    for (int ch = 0; ch < 16; ch++) s += g_xmean_part[((size_t)(b * 16 + ch)) * DIMq + c];
    g_xmean[b * DIMq + c] = s * (1.0f / (float)Tq);
}
__global__ void kimean_kernel(const float* __restrict__ wik) {
    int b = blockIdx.x;
    int d = threadIdx.x;
    float s = 0.f;
    for (int c = 0; c < DIMq; c++) s += g_xmean[b * DIMq + c] * wik[(size_t)c * HDq + d];
    g_kimean[b * HDq + d] = s;
}
__global__ void u_kernel(const float* __restrict__ wiq) {
    int b = blockIdx.x / 16;
    int c = (blockIdx.x % 16) * 128 + threadIdx.x;
    float s = 0.f;
    for (int d = 0; d < HDq; d++) s += wiq[(size_t)c * HDq + d] * g_kimean[b * HDq + d];
    g_u[b * DIMq + c] = s;
}
__global__ void scores_kernel(const float* __restrict__ x) {
    int t = blockIdx.x % NBq;
    int b = blockIdx.x / NBq;
    __shared__ float red[128];
    float s = 0.f;
    const float* xp = x + ((size_t)(b * Tq + t)) * DIMq;
    const float* up = g_u + b * DIMq;
    for (int c = threadIdx.x; c < DIMq; c += 128) s += xp[c] * up[c];
    red[threadIdx.x] = s;
    __syncthreads();
    for (int off = 64; off > 0; off >>= 1) {
        if (threadIdx.x < off) red[threadIdx.x] += red[threadIdx.x + off];
        __syncthreads();
    }
    if (threadIdx.x == 0) g_scores[b * NBq + t] = red[0];
}
__global__ void topk_kernel() {
    int b = blockIdx.x;
    int t = threadIdx.x;
    __shared__ float sc[256];
    sc[t] = g_scores[b * NBq + t];
    __syncthreads();
    float v = sc[t];
    int rank = 0;
    for (int j = 0; j < 256; j++) {
        float o = sc[j];
        rank += (o > v) || (o == v && j < t);
    }
    if (rank < TOPKq) g_topk[b * TOPKq + rank] = t;
}

// ---------------- tensor-core attention ----------------
#define AQ_OFF 0
#define AK_OFF 16384
#define AV_OFF 32768
#define AP_OFF 49152
#define ARM_OFF 57344
#define ARS_OFF 57856
#define ATTN_SMEM2 58368

__global__ __launch_bounds__(256)
void attn_mma() {
    extern __shared__ char sm[];
    const uint32_t base = smem_u32(sm);
    const int tid = threadIdx.x;
    const int wid = tid >> 5;
    const int lane = tid & 31;
    const int ntile = Tq / 64;
    int tile = blockIdx.x % ntile;
    int hk = (blockIdx.x / ntile) % HKVq;
    int b = blockIdx.x / (ntile * HKVq);
    const int bhk = b * HKVq + hk;

    const __half* kp = g_kselh + (size_t)bhk * TOPKq * HDq;
    const __half* vtp = g_vselhT + (size_t)bhk * HDq * TOPKq;

    for (int i = tid; i < 1024; i += 256) {
        int r = i >> 4, c = i & 15;
        *reinterpret_cast<uint4*>(sm + AK_OFF + ((c >> 3) << 13) + (r << 7) +
                                  (((c & 7) ^ (r & 7)) << 4)) =
            *reinterpret_cast<const uint4*>(kp + r * HDq + c * 8);
    }
    for (int i = tid; i < 1024; i += 256) {
        int r = i >> 3, c = i & 7;
        *reinterpret_cast<uint4*>(sm + AV_OFF + (r << 7) + ((c ^ (r & 7)) << 4)) =
            *reinterpret_cast<const uint4*>(vtp + r * TOPKq + c * 8);
    }
    __syncthreads();

    float* redm = reinterpret_cast<float*>(sm + ARM_OFF);
    float* reds = reinterpret_cast<float*>(sm + ARS_OFF);

    const int wm = (wid & 3) << 4;
    const int wn2 = wid >> 2;
    const int g = lane >> 2, tg = lane & 3;
    const int arow = wm + (lane & 15);
    const float scale = 0.08838834764831845f;
    const int qrow0 = b * Tq + tile * 64;

    for (int hi = 0; hi < NREPq; hi++) {
        int h = hk * NREPq + hi;
        for (int i = tid; i < 1024; i += 256) {
            int r = i >> 4, c = i & 15;
            *reinterpret_cast<uint4*>(sm + AQ_OFF + ((c >> 3) << 13) + (r << 7) +
                                      (((c & 7) ^ (r & 7)) << 4)) =
                *reinterpret_cast<const uint4*>(g_qh + (size_t)(qrow0 + r) * DIMq + h * HDq + c * 8);
        }
        __syncthreads();

        float sacc[4][4];
#pragma unroll
        for (int nb = 0; nb < 4; nb++)
#pragma unroll
            for (int c = 0; c < 4; c++) sacc[nb][c] = 0.f;
#pragma unroll
        for (int ks = 0; ks < 8; ks++) {
            int t2 = ks >> 2;
            int kc = ((ks & 3) << 1) + (lane >> 4);
            uint32_t a0, a1, a2, a3;
            ldsm4(a0, a1, a2, a3,
                  base + AQ_OFF + (t2 << 13) + (arow << 7) + ((kc ^ (arow & 7)) << 4));
            uint32_t bf[2][4];
#pragma unroll
            for (int nb2 = 0; nb2 < 2; nb2++) {
                int brw = wn2 * 32 + nb2 * 16 + (lane & 15);
                ldsm4(bf[nb2][0], bf[nb2][1], bf[nb2][2], bf[nb2][3],
                      base + AK_OFF + (t2 << 13) + (brw << 7) + ((kc ^ (brw & 7)) << 4));
            }
#pragma unroll
            for (int nb = 0; nb < 4; nb++) {
                int nb2 = nb >> 1, sel = nb & 1;
                mma16816(sacc[nb][0], sacc[nb][1], sacc[nb][2], sacc[nb][3],
                         a0, a1, a2, a3, bf[nb2][sel], bf[nb2][sel + 2]);
            }
        }
        float m0 = -1e30f, m1 = -1e30f;
#pragma unroll
        for (int nb = 0; nb < 4; nb++) {
#pragma unroll
            for (int c = 0; c < 4; c++) sacc[nb][c] *= scale;
            m0 = fmaxf(m0, fmaxf(sacc[nb][0], sacc[nb][1]));
            m1 = fmaxf(m1, fmaxf(sacc[nb][2], sacc[nb][3]));
        }
        m0 = fmaxf(m0, __shfl_xor_sync(0xffffffffu, m0, 1));
        m0 = fmaxf(m0, __shfl_xor_sync(0xffffffffu, m0, 2));
        m1 = fmaxf(m1, __shfl_xor_sync(0xffffffffu, m1, 1));
        m1 = fmaxf(m1, __shfl_xor_sync(0xffffffffu, m1, 2));
        if (tg == 0) {
            redm[wn2 * 64 + wm + g] = m0;
            redm[wn2 * 64 + wm + g + 8] = m1;
        }
        __syncthreads();
        float M0 = fmaxf(redm[wm + g], redm[64 + wm + g]);
        float M1 = fmaxf(redm[wm + g + 8], redm[64 + wm + g + 8]);
        float s0 = 0.f, s1 = 0.f;
#pragma unroll
        for (int nb = 0; nb < 4; nb++) {
            sacc[nb][0] = expf(sacc[nb][0] - M0);
            sacc[nb][1] = expf(sacc[nb][1] - M0);
            sacc[nb][2] = expf(sacc[nb][2] - M1);
            sacc[nb][3] = expf(sacc[nb][3] - M1);
            s0 += sacc[nb][0] + sacc[nb][1];
            s1 += sacc[nb][2] + sacc[nb][3];
        }
        s0 += __shfl_xor_sync(0xffffffffu, s0, 1);
        s0 += __shfl_xor_sync(0xffffffffu, s0, 2);
        s1 += __shfl_xor_sync(0xffffffffu, s1, 1);
        s1 += __shfl_xor_sync(0xffffffffu, s1, 2);
        if (tg == 0) {
            reds[wn2 * 64 + wm + g] = s0;
            reds[wn2 * 64 + wm + g + 8] = s1;
        }
        __syncthreads();
        float inv0 = 1.f / (reds[wm + g] + reds[64 + wm + g]);
        float inv1 = 1.f / (reds[wm + g + 8] + reds[64 + wm + g + 8]);
#pragma unroll
        for (int nb = 0; nb < 4; nb++) {
            int chunk = wn2 * 4 + nb;
            int r0 = wm + g, r1 = wm + g + 8;
            *reinterpret_cast<__half2*>(sm + AP_OFF + (r0 << 7) +
                                        ((chunk ^ (r0 & 7)) << 4) + (tg << 2)) =
                __floats2half2_rn(sacc[nb][0] * inv0, sacc[nb][1] * inv0);
            *reinterpret_cast<__half2*>(sm + AP_OFF + (r1 << 7) +
                                        ((chunk ^ (r1 & 7)) << 4) + (tg << 2)) =
                __floats2half2_rn(sacc[nb][2] * inv1, sacc[nb][3] * inv1);
        }
        __syncthreads();
        float oacc[8][4];
#pragma unroll
        for (int j = 0; j < 8; j++)
#pragma unroll
            for (int c = 0; c < 4; c++) oacc[j][c] = 0.f;
#pragma unroll
        for (int ks = 0; ks < 4; ks++) {
            int kc = (ks << 1) + (lane >> 4);
            uint32_t a0, a1, a2, a3;
            ldsm4(a0, a1, a2, a3,
                  base + AP_OFF + (arow << 7) + ((kc ^ (arow & 7)) << 4));
            uint32_t bf[4][4];
#pragma unroll
            for (int nb2 = 0; nb2 < 4; nb2++) {
                int brw = wn2 * 64 + nb2 * 16 + (lane & 15);
                ldsm4(bf[nb2][0], bf[nb2][1], bf[nb2][2], bf[nb2][3],
                      base + AV_OFF + (brw << 7) + ((kc ^ (brw & 7)) << 4));
            }
#pragma unroll
            for (int j = 0; j < 8; j++) {
                int nb2 = j >> 1, sel = j & 1;
                mma16816(oacc[j][0], oacc[j][1], oacc[j][2], oacc[j][3],
                         a0, a1, a2, a3, bf[nb2][sel], bf[nb2][sel + 2]);
            }
        }
#pragma unroll
        for (int j = 0; j < 8; j++) {
            int col = wn2 * 64 + (j << 3) + (tg << 1);
            int r0 = tile * 64 + wm + g;
            __half* o0 = g_xoh + (size_t)(b * Tq + r0) * DIMq + h * HDq + col;
            *reinterpret_cast<__half2*>(o0) = __floats2half2_rn(oacc[j][0], oacc[j][1]);
            *reinterpret_cast<__half2*>(o0 + (size_t)8 * DIMq) =
                __floats2half2_rn(oacc[j][2], oacc[j][3]);
        }
        __syncthreads();
    }
}

// ---------------- launch (R11 schedule, fast trig) ----------------
extern "C" void kernel_launch(void* const* d_in, const int* in_sizes, int n_in,
                              void* d_out, int out_size) {
    const float* x   = (const float*)d_in[0];
    const float* wq  = (const float*)d_in[1];
    const float* wk  = (const float*)d_in[2];
    const float* wv  = (const float*)d_in[3];
    const float* wo  = (const float*)d_in[4];
    const float* wiq = (const float*)d_in[5];
    const float* wik = (const float*)d_in[6];
    const float* cwa = (const float*)d_in[7];
    const float* cwb = (const float*)d_in[8];
    float* out = (float*)d_out;

    static cudaStream_t s2 = nullptr, s3 = nullptr;
    static cudaEvent_t eFork = nullptr, eT = nullptr, eKV = nullptr, eGa = nullptr, eWo = nullptr;
    if (!s2) {
        cudaStreamCreateWithFlags(&s2, cudaStreamNonBlocking);
        cudaStreamCreateWithFlags(&s3, cudaStreamNonBlocking);
        cudaEventCreateWithFlags(&eFork, cudaEventDisableTiming);
        cudaEventCreateWithFlags(&eT, cudaEventDisableTiming);
        cudaEventCreateWithFlags(&eKV, cudaEventDisableTiming);
        cudaEventCreateWithFlags(&eGa, cudaEventDisableTiming);
        cudaEventCreateWithFlags(&eWo, cudaEventDisableTiming);
        cudaFuncSetAttribute(gemm_qkv, cudaFuncAttributeMaxDynamicSharedMemorySize, GEMM_SMEM);
        cudaFuncSetAttribute(gemm_f16, cudaFuncAttributeMaxDynamicSharedMemorySize, GEMM_SMEM);
        cudaFuncSetAttribute(attn_mma, cudaFuncAttributeMaxDynamicSharedMemorySize, ATTN_SMEM2);
    }

    __half *xh, *xoh, *wqkvT, *woT;
    cudaGetSymbolAddress((void**)&xh, g_xh);
    cudaGetSymbolAddress((void**)&xoh, g_xoh);
    cudaGetSymbolAddress((void**)&wqkvT, g_wqkvT);
    cudaGetSymbolAddress((void**)&woT, g_woT);

    // fork
    cudaEventRecord(eFork, 0);
    cudaStreamWaitEvent(s2, eFork, 0);
    cudaStreamWaitEvent(s3, eFork, 0);

    // s2: fast trig + QKV weight transposes
    trig_table_kernel<<<(Tq * 64 + 255) / 256, 256, 0, s2>>>();
    transpose_h<<<dim3(DIMq / 32, DIMq / 32), dim3(32, 8), 0, s2>>>(wq, wqkvT, DIMq, DIMq);
    transpose_h<<<dim3((HKVq * HDq) / 32, DIMq / 32), dim3(32, 8), 0, s2>>>(
        wk, wqkvT + (size_t)2048 * DIMq, DIMq, HKVq * HDq);
    transpose_h<<<dim3((HKVq * HDq) / 32, DIMq / 32), dim3(32, 8), 0, s2>>>(
        wv, wqkvT + (size_t)2560 * DIMq, DIMq, HKVq * HDq);
    cudaEventRecord(eT, s2);

    // main: conv + KV GEMM
    conv_h<<<2048, 256>>>(x, xh, (size_t)Mq * DIMq);
    cudaStreamWaitEvent(0, eT, 0);
    gemm_qkv<<<dim3(8, Mq / 128), 256, GEMM_SMEM>>>(xh, wqkvT, 16);   // K, V
    cudaEventRecord(eKV, 0);

    // s2 tail: wo transpose (overlaps main GEMMs)
    transpose_h<<<dim3(DIMq / 32, DIMq / 32), dim3(32, 8), 0, s2>>>(wo, woT, DIMq, DIMq);
    cudaEventRecord(eWo, s2);

    // s3: selection chain + selected-only compress (waits eKV; enqueued after its record)
    xmean_part_kernel<<<dim3(16, 16, Bq), 128, 0, s3>>>(x);
    xmean_final_kernel<<<Bq * 16, 128, 0, s3>>>();
    kimean_kernel<<<Bq, 128, 0, s3>>>(wik);
    u_kernel<<<Bq * 16, 128, 0, s3>>>(wiq);
    scores_kernel<<<Bq * NBq, 128, 0, s3>>>(x);
    topk_kernel<<<Bq, 256, 0, s3>>>();
    cudaStreamWaitEvent(s3, eKV, 0);
    compress_sel<<<Bq * HKVq * TOPKq, 128, 0, s3>>>(cwa, cwb);
    cudaEventRecord(eGa, s3);

    // main: Q GEMM overlaps compress; then attention; then output GEMM
    gemm_qkv<<<dim3(16, Mq / 128), 256, GEMM_SMEM>>>(xh, wqkvT, 0);   // Q
    cudaStreamWaitEvent(0, eGa, 0);
    attn_mma<<<Bq * HKVq * (Tq / 64), 256, ATTN_SMEM2>>>();
    cudaStreamWaitEvent(0, eWo, 0);
    gemm_f16<<<dim3(DIMq / 128, Mq / 128), 256, GEMM_SMEM>>>(xoh, woT, out, DIMq, DIMq);
}

// round 15
// speedup vs baseline: 1.1372x; 1.0182x over previous
#include <cuda_runtime.h>
#include <cuda_fp16.h>
#include <math.h>
#include <cstdint>

#define Bq 2
#define Tq 4096
#define DIMq 2048
#define Hq 16
#define HKVq 4
#define HDq 128
#define NREPq 4
#define Rq 16
#define NBq 256
#define TOPKq 64
#define Mq (Bq * Tq)
#define NQKV 3072

// ---------------- scratch ----------------
__device__ __half g_k[Mq * HKVq * HDq];
__device__ __half g_v[Mq * HKVq * HDq];
__device__ float g_xmean_part[Bq * 16 * DIMq];
__device__ float g_xmean[Bq * DIMq];
__device__ float g_kimean[Bq * HDq];
__device__ float g_u[Bq * DIMq];
__device__ float g_scores[Bq * NBq];
__device__ int   g_topk[Bq * TOPKq];
__device__ float2 g_trig[Tq * 64];

__device__ __half g_qh[Mq * DIMq];
__device__ __half g_kselh[Bq * HKVq * TOPKq * HDq];
__device__ __half g_vselhT[Bq * HKVq * HDq * TOPKq];
__device__ __half g_xh[Mq * DIMq];
__device__ __half g_xoh[Mq * DIMq];
__device__ __half g_wqkvT[NQKV * DIMq];
__device__ __half g_woT[DIMq * DIMq];

// ---------------- helpers ----------------
__device__ __forceinline__ uint32_t smem_u32(const void* p) {
    uint32_t a;
    asm("{ .reg .u64 t; cvta.to.shared.u64 t, %1; cvt.u32.u64 %0, t; }" : "=r"(a) : "l"(p));
    return a;
}
__device__ __forceinline__ void cp16(uint32_t dst, const void* src) {
    asm volatile("cp.async.cg.shared.global [%0], [%1], 16;" :: "r"(dst), "l"(src));
}
__device__ __forceinline__ void ldsm4(uint32_t& r0, uint32_t& r1, uint32_t& r2, uint32_t& r3,
                                      uint32_t addr) {
    asm volatile("ldmatrix.sync.aligned.m8n8.x4.shared.b16 {%0,%1,%2,%3}, [%4];"
                 : "=r"(r0), "=r"(r1), "=r"(r2), "=r"(r3) : "r"(addr));
}
__device__ __forceinline__ void mma16816(float& c0, float& c1, float& c2, float& c3,
                                         uint32_t a0, uint32_t a1, uint32_t a2, uint32_t a3,
                                         uint32_t b0, uint32_t b1) {
    asm volatile(
        "mma.sync.aligned.m16n8k16.row.col.f32.f16.f16.f32 "
        "{%0,%1,%2,%3}, {%4,%5,%6,%7}, {%8,%9}, {%0,%1,%2,%3};"
        : "+f"(c0), "+f"(c1), "+f"(c2), "+f"(c3)
        : "r"(a0), "r"(a1), "r"(a2), "r"(a3), "r"(b0), "r"(b1));
}

// ---------------- GEMM core ----------------
#define NSTAGE 3
#define STAGE_BYTES 32768
#define GEMM_SMEM (NSTAGE * STAGE_BYTES)

#define GEMM_MAINLOOP(A_, Bt_, K_)                                                  \
    const int nchunks = (K_) >> 6;                                                  \
    const int wm = (wid & 3) << 5;                                                  \
    const int wn = (wid >> 2) << 6;                                                 \
    float acc[2][8][4];                                                             \
    _Pragma("unroll") for (int i = 0; i < 2; i++)                                   \
        _Pragma("unroll") for (int j = 0; j < 8; j++)                               \
            _Pragma("unroll") for (int c = 0; c < 4; c++) acc[i][j][c] = 0.f;       \
    auto produce = [&](int ci) {                                                    \
        const int slot = ci % NSTAGE;                                               \
        const int kk = ci << 6;                                                     \
        const uint32_t sA = tiles + slot * STAGE_BYTES;                             \
        const uint32_t sB = sA + 16384;                                             \
        _Pragma("unroll") for (int i = 0; i < 4; i++) {                             \
            int ch = tid + (i << 8);                                                \
            int row = ch >> 3;                                                      \
            int c = ch & 7;                                                         \
            uint32_t soff = (row << 7) + (((c ^ (row & 7))) << 4);                  \
            cp16(sA + soff, (A_) + (size_t)(brow + row) * (K_) + kk + c * 8);       \
            cp16(sB + soff, (Bt_) + (size_t)(bcol + row) * (K_) + kk + c * 8);      \
        }                                                                           \
        asm volatile("cp.async.commit_group;" ::: "memory");                        \
    };                                                                              \
    produce(0);                                                                     \
    produce(1);                                                                     \
    for (int ci = 0; ci < nchunks; ci++) {                                          \
        if (ci + 1 < nchunks)                                                       \
            asm volatile("cp.async.wait_group 1;" ::: "memory");                    \
        else                                                                        \
            asm volatile("cp.async.wait_group 0;" ::: "memory");                    \
        __syncthreads();                                                            \
        if (ci + 2 < nchunks) produce(ci + 2);                                      \
        const int slot = ci % NSTAGE;                                               \
        const uint32_t sA = tiles + slot * STAGE_BYTES;                             \
        const uint32_t sB = sA + 16384;                                             \
        _Pragma("unroll") for (int ks = 0; ks < 4; ks++) {                          \
            const int kc = (ks << 1) + (lane >> 4);                                 \
            uint32_t a[2][4];                                                       \
            _Pragma("unroll") for (int ma = 0; ma < 2; ma++) {                      \
                int row = wm + (ma << 4) + (lane & 15);                             \
                uint32_t addr = sA + (row << 7) + ((kc ^ (row & 7)) << 4);          \
                ldsm4(a[ma][0], a[ma][1], a[ma][2], a[ma][3], addr);                \
            }                                                                       \
            uint32_t b[4][4];                                                       \
            _Pragma("unroll") for (int nb = 0; nb < 4; nb++) {                      \
                int row = wn + (nb << 4) + (lane & 15);                             \
                uint32_t addr = sB + (row << 7) + ((kc ^ (row & 7)) << 4);          \
                ldsm4(b[nb][0], b[nb][1], b[nb][2], b[nb][3], addr);                \
            }                                                                       \
            _Pragma("unroll") for (int ma = 0; ma < 2; ma++)                        \
                _Pragma("unroll") for (int j = 0; j < 8; j++) {                     \
                    int nb = j >> 1, sel = j & 1;                                   \
                    mma16816(acc[ma][j][0], acc[ma][j][1], acc[ma][j][2],           \
                             acc[ma][j][3], a[ma][0], a[ma][1], a[ma][2],           \
                             a[ma][3], b[nb][sel], b[nb][sel + 2]);                 \
                }                                                                   \
        }                                                                           \
    }

// fused QKV projection + RoPE epilogue; bcol0 selects Q (0) vs KV (16) launch
__global__ __launch_bounds__(256, 2)
void gemm_qkv(const __half* __restrict__ A, const __half* __restrict__ Bt, int bcol0) {
    extern __shared__ char smem[];
    const uint32_t tiles = smem_u32(smem);
    const int tid = threadIdx.x;
    const int wid = tid >> 5;
    const int lane = tid & 31;
    const int brow = blockIdx.y << 7;
    const int bcol = (blockIdx.x + bcol0) << 7;

    GEMM_MAINLOOP(A, Bt, DIMq)

    const int g = lane >> 2;
    const int tg = lane & 3;
    __half* Cout;
    int cbase, cstride;
    bool dorope;
    if (bcol < 2048)      { Cout = g_qh; cbase = bcol;        cstride = 2048; dorope = true; }
    else if (bcol < 2560) { Cout = g_k;  cbase = bcol - 2048; cstride = 512;  dorope = true; }
    else                  { Cout = g_v;  cbase = bcol - 2560; cstride = 512;  dorope = false; }
#pragma unroll
    for (int ma = 0; ma < 2; ma++) {
#pragma unroll
        for (int j = 0; j < 8; j++) {
            int row = brow + wm + (ma << 4) + g;
            int col = cbase + wn + (j << 3) + (tg << 1);
            float2 lo = make_float2(acc[ma][j][0], acc[ma][j][1]);
            float2 hi = make_float2(acc[ma][j][2], acc[ma][j][3]);
            if (dorope) {
                int p = (col & 127) >> 1;
                float2 c1 = g_trig[((row & (Tq - 1)) << 6) + p];
                float2 c2 = g_trig[(((row + 8) & (Tq - 1)) << 6) + p];
                lo = make_float2(lo.x * c1.x - lo.y * c1.y, lo.x * c1.y + lo.y * c1.x);
                hi = make_float2(hi.x * c2.x - hi.y * c2.y, hi.x * c2.y + hi.y * c2.x);
            }
            *reinterpret_cast<__half2*>(Cout + (size_t)row * cstride + col) =
                __floats2half2_rn(lo.x, lo.y);
            *reinterpret_cast<__half2*>(Cout + (size_t)(row + 8) * cstride + col) =
                __floats2half2_rn(hi.x, hi.y);
        }
    }
}

// generic GEMM (output projection)
__global__ __launch_bounds__(256, 2)
void gemm_f16(const __half* __restrict__ A, const __half* __restrict__ Bt,
              float* __restrict__ C, int N, int K) {
    extern __shared__ char smem[];
    const uint32_t tiles = smem_u32(smem);
    const int tid = threadIdx.x;
    const int wid = tid >> 5;
    const int lane = tid & 31;
    const int brow = blockIdx.y << 7;
    const int bcol = blockIdx.x << 7;

    GEMM_MAINLOOP(A, Bt, K)

    const int g = lane >> 2;
    const int tg = lane & 3;
#pragma unroll
    for (int ma = 0; ma < 2; ma++) {
#pragma unroll
        for (int j = 0; j < 8; j++) {
            int row = brow + wm + (ma << 4) + g;
            int col = bcol + wn + (j << 3) + (tg << 1);
            float2 lo = make_float2(acc[ma][j][0], acc[ma][j][1]);
            float2 hi = make_float2(acc[ma][j][2], acc[ma][j][3]);
            *reinterpret_cast<float2*>(C + (size_t)row * N + col) = lo;
            *reinterpret_cast<float2*>(C + (size_t)(row + 8) * N + col) = hi;
        }
    }
}

// ---------------- fp32 -> fp16 convert ----------------
__global__ void conv_h(const float* __restrict__ src, __half* __restrict__ dst, size_t n) {
    size_t i = ((size_t)blockIdx.x * blockDim.x + threadIdx.x) * 4;
    size_t stride = (size_t)gridDim.x * blockDim.x * 4;
    for (; i < n; i += stride) {
        float4 v = *reinterpret_cast<const float4*>(src + i);
        *reinterpret_cast<__half2*>(dst + i) = __floats2half2_rn(v.x, v.y);
        *reinterpret_cast<__half2*>(dst + i + 2) = __floats2half2_rn(v.z, v.w);
    }
}

// transpose + convert: w [K,N] fp32 -> wT [N,K] fp16
__global__ void transpose_h(const float* __restrict__ w, __half* __restrict__ wT,
                            int K, int N) {
    __shared__ float t[32][33];
    int n0 = blockIdx.x << 5, k0 = blockIdx.y << 5;
    int tx = threadIdx.x, ty = threadIdx.y;
#pragma unroll
    for (int j = 0; j < 4; j++)
        t[ty + j * 8][tx] = w[(size_t)(k0 + ty + j * 8) * N + n0 + tx];
    __syncthreads();
#pragma unroll
    for (int j = 0; j < 4; j++) {
        int n = n0 + ty + j * 8;
        wT[(size_t)n * K + k0 + tx] = __float2half(t[tx][ty + j * 8]);
    }
}

// ---------------- fast trig table ----------------
__global__ void trig_table_kernel() {
    __shared__ double freqs[64];
    int idx = blockIdx.x * blockDim.x + threadIdx.x;
    if (threadIdx.x < 64) {
        int p = threadIdx.x;
        freqs[p] = exp(-((double)p / 64.0) * log(10000.0));
    }
    __syncthreads();
    if (idx >= Tq * 64) return;
    int p = idx & 63;
    int t = idx >> 6;
    double ang = (double)t * freqs[p];
    const double twopi = 6.283185307179586476925286766559;
    double k = floor(ang * (1.0 / twopi));
    float r = (float)(ang - k * twopi);
    float sf, cf;
    sincosf(r, &sf, &cf);
    g_trig[idx] = make_float2(cf, sf);
}

// ---------------- compress only selected blocks ----------------
__global__ void compress_sel(const float* __restrict__ cwa, const float* __restrict__ cwb) {
    int j = blockIdx.x % TOPKq;
    int hk = (blockIdx.x / TOPKq) % HKVq;
    int b = blockIdx.x / (TOPKq * HKVq);
    int bhk = b * HKVq + hk;
    int n = g_topk[b * TOPKq + j];
    __shared__ float kb[Rq][HDq + 4];
    __shared__ float vb[Rq][HDq + 4];
    __shared__ float sa[Rq], sb[Rq], w[Rq];
    int d = threadIdx.x;
    for (int r = 0; r < Rq; r++) {
        int t = n * Rq + r;
        size_t off = ((size_t)(b * Tq + t)) * (HKVq * HDq) + hk * HDq + d;
        kb[r][d] = __half2float(g_k[off]);
        vb[r][d] = __half2float(g_v[off]);
    }
    __syncthreads();
    {
        int grp = d >> 3, sub = d & 7;
        float da = 0.f, db = 0.f;
        for (int i = sub; i < HDq; i += 8) {
            float kv = kb[grp][i];
            da = fmaf(kv, __ldg(cwa + i), da);
            db = fmaf(kv, __ldg(cwb + i), db);
        }
#pragma unroll
        for (int o = 4; o > 0; o >>= 1) {
            da += __shfl_down_sync(0xffffffffu, da, o, 8);
            db += __shfl_down_sync(0xffffffffu, db, o, 8);
        }
        if (sub == 0) { sa[grp] = da; sb[grp] = db; }
    }
    __syncthreads();
    if (d < 16) {
        float a = sa[d], bb = sb[d];
        float ma = a, mb = bb;
#pragma unroll
        for (int o = 8; o > 0; o >>= 1) {
            ma = fmaxf(ma, __shfl_xor_sync(0x0000ffffu, ma, o, 16));
            mb = fmaxf(mb, __shfl_xor_sync(0x0000ffffu, mb, o, 16));
        }
        float ea = expf(a - ma), eb = expf(bb - mb);
        float sua = ea, sub2 = eb;
#pragma unroll
        for (int o = 8; o > 0; o >>= 1) {
            sua += __shfl_xor_sync(0x0000ffffu, sua, o, 16);
            sub2 += __shfl_xor_sync(0x0000ffffu, sub2, o, 16);
        }
        w[d] = 0.5f * (ea / sua + eb / sub2);
    }
    __syncthreads();
    float ck = 0.f, cv = 0.f;
#pragma unroll
    for (int r = 0; r < Rq; r++) {
        ck = fmaf(w[r], kb[r][d], ck);
        cv = fmaf(w[r], vb[r][d], cv);
    }
    g_kselh[((size_t)bhk * TOPKq + j) * HDq + d] = __float2half(ck);
    g_vselhT[(size_t)bhk * HDq * TOPKq + (size_t)d * TOPKq + j] = __float2half(cv);
}

// ---------------- selection chain ----------------
__global__ void xmean_part_kernel(const float* __restrict__ x) {
    int b = blockIdx.z;
    int chunk = blockIdx.y;
    int c = blockIdx.x * 128 + threadIdx.x;
    float s = 0.f;
    for (int tt = chunk * 256; tt < (chunk + 1) * 256; tt++)
        s += x[((size_t)(b * Tq + tt)) * DIMq + c];
    g_xmean_part[((size_t)(b * 16 + chunk)) * DIMq + c] = s;
}
__global__ void xmean_final_kernel() {
    int b = blockIdx.x / 16;
    int c = (blockIdx.x % 16) * 128 + threadIdx.x;
    float s = 0.f;
    for (int ch = 0; ch < 16; ch++) s += g_xmean_part[((size_t)(b * 16 + ch)) * DIMq + c];
    g_xmean[b * DIMq + c] = s * (1.0f / (float)Tq);
}
__global__ void kimean_kernel(const float* __restrict__ wik) {
    int b = blockIdx.x;
    int d = threadIdx.x;
    float s = 0.f;
    for (int c = 0; c < DIMq; c++) s += g_xmean[b * DIMq + c] * wik[(size_t)c * HDq + d];
    g_kimean[b * HDq + d] = s;
}
__global__ void u_kernel(const float* __restrict__ wiq) {
    int b = blockIdx.x / 16;
    int c = (blockIdx.x % 16) * 128 + threadIdx.x;
    float s = 0.f;
    for (int d = 0; d < HDq; d++) s += wiq[(size_t)c * HDq + d] * g_kimean[b * HDq + d];
    g_u[b * DIMq + c] = s;
}
__global__ void scores_kernel(const float* __restrict__ x) {
    int t = blockIdx.x % NBq;
    int b = blockIdx.x / NBq;
    __shared__ float red[128];
    float s = 0.f;
    const float* xp = x + ((size_t)(b * Tq + t)) * DIMq;
    const float* up = g_u + b * DIMq;
    for (int c = threadIdx.x; c < DIMq; c += 128) s += xp[c] * up[c];
    red[threadIdx.x] = s;
    __syncthreads();
    for (int off = 64; off > 0; off >>= 1) {
        if (threadIdx.x < off) red[threadIdx.x] += red[threadIdx.x + off];
        __syncthreads();
    }
    if (threadIdx.x == 0) g_scores[b * NBq + t] = red[0];
}
__global__ void topk_kernel() {
    int b = blockIdx.x;
    int t = threadIdx.x;
    __shared__ float sc[256];
    sc[t] = g_scores[b * NBq + t];
    __syncthreads();
    float v = sc[t];
    int rank = 0;
    for (int j = 0; j < 256; j++) {
        float o = sc[j];
        rank += (o > v) || (o == v && j < t);
    }
    if (rank < TOPKq) g_topk[b * TOPKq + rank] = t;
}

// ---------------- tensor-core attention (double-buffered Q via cp.async) ----------------
#define AQ0_OFF 0
#define AQ1_OFF 16384
#define AK_OFF 32768
#define AV_OFF 49152
#define AP_OFF 65536
#define ARM_OFF 73728
#define ARS_OFF 74240
#define ATTN_SMEM2 74752

__global__ __launch_bounds__(256)
void attn_mma() {
    extern __shared__ char sm[];
    const uint32_t base = smem_u32(sm);
    const int tid = threadIdx.x;
    const int wid = tid >> 5;
    const int lane = tid & 31;
    const int ntile = Tq / 64;
    int tile = blockIdx.x % ntile;
    int hk = (blockIdx.x / ntile) % HKVq;
    int b = blockIdx.x / (ntile * HKVq);
    const int bhk = b * HKVq + hk;

    const __half* kp = g_kselh + (size_t)bhk * TOPKq * HDq;
    const __half* vtp = g_vselhT + (size_t)bhk * HDq * TOPKq;
    const int qrow0 = b * Tq + tile * 64;
    const int h0 = hk * NREPq;

    // Q staging helper: head h into buffer qoff (4 cp.async per thread)
    auto stage_q = [&](int h, uint32_t qoff) {
#pragma unroll
        for (int i = 0; i < 4; i++) {
            int idx = tid + (i << 8);
            int r = idx >> 4, c = idx & 15;
            cp16(base + qoff + ((c >> 3) << 13) + (r << 7) + (((c & 7) ^ (r & 7)) << 4),
                 g_qh + (size_t)(qrow0 + r) * DIMq + h * HDq + c * 8);
        }
        asm volatile("cp.async.commit_group;" ::: "memory");
    };

    // group 0: K (4/thread) + V (4/thread) + Q(head0)
#pragma unroll
    for (int i = 0; i < 4; i++) {
        int idx = tid + (i << 8);
        int r = idx >> 4, c = idx & 15;
        cp16(base + AK_OFF + ((c >> 3) << 13) + (r << 7) + (((c & 7) ^ (r & 7)) << 4),
             kp + r * HDq + c * 8);
    }
#pragma unroll
    for (int i = 0; i < 4; i++) {
        int idx = tid + (i << 8);
        int r = idx >> 3, c = idx & 7;
        cp16(base + AV_OFF + (r << 7) + ((c ^ (r & 7)) << 4), vtp + r * TOPKq + c * 8);
    }
    stage_q(h0, AQ0_OFF);

    float* redm = reinterpret_cast<float*>(sm + ARM_OFF);
    float* reds = reinterpret_cast<float*>(sm + ARS_OFF);

    const int wm = (wid & 3) << 4;
    const int wn2 = wid >> 2;
    const int g = lane >> 2, tg = lane & 3;
    const int arow = wm + (lane & 15);
    const float scale = 0.08838834764831845f;

    for (int hi = 0; hi < NREPq; hi++) {
        int h = h0 + hi;
        const uint32_t qoff = (hi & 1) ? AQ1_OFF : AQ0_OFF;
        // wait for K/V + Q(hi) (and any prior prefetch), then sync
        asm volatile("cp.async.wait_group 0;" ::: "memory");
        __syncthreads();
        // prefetch next head's Q into the other buffer (hidden under compute)
        if (hi + 1 < NREPq) stage_q(h0 + hi + 1, (hi & 1) ? AQ0_OFF : AQ1_OFF);

        // S = Q @ K^T (64x64)
        float sacc[4][4];
#pragma unroll
        for (int nb = 0; nb < 4; nb++)
#pragma unroll
            for (int c = 0; c < 4; c++) sacc[nb][c] = 0.f;
#pragma unroll
        for (int ks = 0; ks < 8; ks++) {
            int t2 = ks >> 2;
            int kc = ((ks & 3) << 1) + (lane >> 4);
            uint32_t a0, a1, a2, a3;
            ldsm4(a0, a1, a2, a3,
                  base + qoff + (t2 << 13) + (arow << 7) + ((kc ^ (arow & 7)) << 4));
            uint32_t bf[2][4];
#pragma unroll
            for (int nb2 = 0; nb2 < 2; nb2++) {
                int brw = wn2 * 32 + nb2 * 16 + (lane & 15);
                ldsm4(bf[nb2][0], bf[nb2][1], bf[nb2][2], bf[nb2][3],
                      base + AK_OFF + (t2 << 13) + (brw << 7) + ((kc ^ (brw & 7)) << 4));
            }
#pragma unroll
            for (int nb = 0; nb < 4; nb++) {
                int nb2 = nb >> 1, sel = nb & 1;
                mma16816(sacc[nb][0], sacc[nb][1], sacc[nb][2], sacc[nb][3],
                         a0, a1, a2, a3, bf[nb2][sel], bf[nb2][sel + 2]);
            }
        }
        float m0 = -1e30f, m1 = -1e30f;
#pragma unroll
        for (int nb = 0; nb < 4; nb++) {
#pragma unroll
            for (int c = 0; c < 4; c++) sacc[nb][c] *= scale;
            m0 = fmaxf(m0, fmaxf(sacc[nb][0], sacc[nb][1]));
            m1 = fmaxf(m1, fmaxf(sacc[nb][2], sacc[nb][3]));
        }
        m0 = fmaxf(m0, __shfl_xor_sync(0xffffffffu, m0, 1));
        m0 = fmaxf(m0, __shfl_xor_sync(0xffffffffu, m0, 2));
        m1 = fmaxf(m1, __shfl_xor_sync(0xffffffffu, m1, 1));
        m1 = fmaxf(m1, __shfl_xor_sync(0xffffffffu, m1, 2));
        if (tg == 0) {
            redm[wn2 * 64 + wm + g] = m0;
            redm[wn2 * 64 + wm + g + 8] = m1;
        }
        __syncthreads();
        float M0 = fmaxf(redm[wm + g], redm[64 + wm + g]);
        float M1 = fmaxf(redm[wm + g + 8], redm[64 + wm + g + 8]);
        float s0 = 0.f, s1 = 0.f;
#pragma unroll
        for (int nb = 0; nb < 4; nb++) {
            sacc[nb][0] = expf(sacc[nb][0] - M0);
            sacc[nb][1] = expf(sacc[nb][1] - M0);
            sacc[nb][2] = expf(sacc[nb][2] - M1);
            sacc[nb][3] = expf(sacc[nb][3] - M1);
            s0 += sacc[nb][0] + sacc[nb][1];
            s1 += sacc[nb][2] + sacc[nb][3];
        }
        s0 += __shfl_xor_sync(0xffffffffu, s0, 1);
        s0 += __shfl_xor_sync(0xffffffffu, s0, 2);
        s1 += __shfl_xor_sync(0xffffffffu, s1, 1);
        s1 += __shfl_xor_sync(0xffffffffu, s1, 2);
        if (tg == 0) {
            reds[wn2 * 64 + wm + g] = s0;
            reds[wn2 * 64 + wm + g + 8] = s1;
        }
        __syncthreads();
        float inv0 = 1.f / (reds[wm + g] + reds[64 + wm + g]);
        float inv1 = 1.f / (reds[wm + g + 8] + reds[64 + wm + g + 8]);
#pragma unroll
        for (int nb = 0; nb < 4; nb++) {
            int chunk = wn2 * 4 + nb;
            int r0 = wm + g, r1 = wm + g + 8;
            *reinterpret_cast<__half2*>(sm + AP_OFF + (r0 << 7) +
                                        ((chunk ^ (r0 & 7)) << 4) + (tg << 2)) =
                __floats2half2_rn(sacc[nb][0] * inv0, sacc[nb][1] * inv0);
            *reinterpret_cast<__half2*>(sm + AP_OFF + (r1 << 7) +
                                        ((chunk ^ (r1 & 7)) << 4) + (tg << 2)) =
                __floats2half2_rn(sacc[nb][2] * inv1, sacc[nb][3] * inv1);
        }
        __syncthreads();
        float oacc[8][4];
#pragma unroll
        for (int j = 0; j < 8; j++)
#pragma unroll
            for (int c = 0; c < 4; c++) oacc[j][c] = 0.f;
#pragma unroll
        for (int ks = 0; ks < 4; ks++) {
            int kc = (ks << 1) + (lane >> 4);
            uint32_t a0, a1, a2, a3;
            ldsm4(a0, a1, a2, a3,
                  base + AP_OFF + (arow << 7) + ((kc ^ (arow & 7)) << 4));
            uint32_t bf[4][4];
#pragma unroll
            for (int nb2 = 0; nb2 < 4; nb2++) {
                int brw = wn2 * 64 + nb2 * 16 + (lane & 15);
                ldsm4(bf[nb2][0], bf[nb2][1], bf[nb2][2], bf[nb2][3],
                      base + AV_OFF + (brw << 7) + ((kc ^ (brw & 7)) << 4));
            }
#pragma unroll
            for (int j = 0; j < 8; j++) {
                int nb2 = j >> 1, sel = j & 1;
                mma16816(oacc[j][0], oacc[j][1], oacc[j][2], oacc[j][3],
                         a0, a1, a2, a3, bf[nb2][sel], bf[nb2][sel + 2]);
            }
        }
#pragma unroll
        for (int j = 0; j < 8; j++) {
            int col = wn2 * 64 + (j << 3) + (tg << 1);
            int r0 = tile * 64 + wm + g;
            __half* o0 = g_xoh + (size_t)(b * Tq + r0) * DIMq + h * HDq + col;
            *reinterpret_cast<__half2*>(o0) = __floats2half2_rn(oacc[j][0], oacc[j][1]);
            *reinterpret_cast<__half2*>(o0 + (size_t)8 * DIMq) =
                __floats2half2_rn(oacc[j][2], oacc[j][3]);
        }
        __syncthreads();
    }
}

// ---------------- launch (R14 schedule) ----------------
extern "C" void kernel_launch(void* const* d_in, const int* in_sizes, int n_in,
                              void* d_out, int out_size) {
    const float* x   = (const float*)d_in[0];
    const float* wq  = (const float*)d_in[1];
    const float* wk  = (const float*)d_in[2];
    const float* wv  = (const float*)d_in[3];
    const float* wo  = (const float*)d_in[4];
    const float* wiq = (const float*)d_in[5];
    const float* wik = (const float*)d_in[6];
    const float* cwa = (const float*)d_in[7];
    const float* cwb = (const float*)d_in[8];
    float* out = (float*)d_out;

    static cudaStream_t s2 = nullptr, s3 = nullptr;
    static cudaEvent_t eFork = nullptr, eT = nullptr, eKV = nullptr, eGa = nullptr, eWo = nullptr;
    if (!s2) {
        cudaStreamCreateWithFlags(&s2, cudaStreamNonBlocking);
        cudaStreamCreateWithFlags(&s3, cudaStreamNonBlocking);
        cudaEventCreateWithFlags(&eFork, cudaEventDisableTiming);
        cudaEventCreateWithFlags(&eT, cudaEventDisableTiming);
        cudaEventCreateWithFlags(&eKV, cudaEventDisableTiming);
        cudaEventCreateWithFlags(&eGa, cudaEventDisableTiming);
        cudaEventCreateWithFlags(&eWo, cudaEventDisableTiming);
        cudaFuncSetAttribute(gemm_qkv, cudaFuncAttributeMaxDynamicSharedMemorySize, GEMM_SMEM);
        cudaFuncSetAttribute(gemm_f16, cudaFuncAttributeMaxDynamicSharedMemorySize, GEMM_SMEM);
        cudaFuncSetAttribute(attn_mma, cudaFuncAttributeMaxDynamicSharedMemorySize, ATTN_SMEM2);
    }

    __half *xh, *xoh, *wqkvT, *woT;
    cudaGetSymbolAddress((void**)&xh, g_xh);
    cudaGetSymbolAddress((void**)&xoh, g_xoh);
    cudaGetSymbolAddress((void**)&wqkvT, g_wqkvT);
    cudaGetSymbolAddress((void**)&woT, g_woT);

    // fork
    cudaEventRecord(eFork, 0);
    cudaStreamWaitEvent(s2, eFork, 0);
    cudaStreamWaitEvent(s3, eFork, 0);

    // s2: fast trig + QKV weight transposes
    trig_table_kernel<<<(Tq * 64 + 255) / 256, 256, 0, s2>>>();
    transpose_h<<<dim3(DIMq / 32, DIMq / 32), dim3(32, 8), 0, s2>>>(wq, wqkvT, DIMq, DIMq);
    transpose_h<<<dim3((HKVq * HDq) / 32, DIMq / 32), dim3(32, 8), 0, s2>>>(
        wk, wqkvT + (size_t)2048 * DIMq, DIMq, HKVq * HDq);
    transpose_h<<<dim3((HKVq * HDq) / 32, DIMq / 32), dim3(32, 8), 0, s2>>>(
        wv, wqkvT + (size_t)2560 * DIMq, DIMq, HKVq * HDq);
    cudaEventRecord(eT, s2);

    // main: conv + KV GEMM
    conv_h<<<2048, 256>>>(x, xh, (size_t)Mq * DIMq);
    cudaStreamWaitEvent(0, eT, 0);
    gemm_qkv<<<dim3(8, Mq / 128), 256, GEMM_SMEM>>>(xh, wqkvT, 16);   // K, V
    cudaEventRecord(eKV, 0);

    // s2 tail: wo transpose (overlaps main GEMMs)
    transpose_h<<<dim3(DIMq / 32, DIMq / 32), dim3(32, 8), 0, s2>>>(wo, woT, DIMq, DIMq);
    cudaEventRecord(eWo, s2);

    // s3: selection chain + selected-only compress (waits eKV; enqueued after its record)
    xmean_part_kernel<<<dim3(16, 16, Bq), 128, 0, s3>>>(x);
    xmean_final_kernel<<<Bq * 16, 128, 0, s3>>>();
    kimean_kernel<<<Bq, 128, 0, s3>>>(wik);
    u_kernel<<<Bq * 16, 128, 0, s3>>>(wiq);
    scores_kernel<<<Bq * NBq, 128, 0, s3>>>(x);
    topk_kernel<<<Bq, 256, 0, s3>>>();
    cudaStreamWaitEvent(s3, eKV, 0);
    compress_sel<<<Bq * HKVq * TOPKq, 128, 0, s3>>>(cwa, cwb);
    cudaEventRecord(eGa, s3);

    // main: Q GEMM overlaps compress; then attention; then output GEMM
    gemm_qkv<<<dim3(16, Mq / 128), 256, GEMM_SMEM>>>(xh, wqkvT, 0);   // Q
    cudaStreamWaitEvent(0, eGa, 0);
    attn_mma<<<Bq * HKVq * (Tq / 64), 256, ATTN_SMEM2>>>();
    cudaStreamWaitEvent(0, eWo, 0);
    gemm_f16<<<dim3(DIMq / 128, Mq / 128), 256, GEMM_SMEM>>>(xoh, woT, out, DIMq, DIMq);
}